// round 1
// baseline (speedup 1.0000x reference)
#include <cuda_runtime.h>
#include <math.h>

// ---------------------------------------------------------------------------
// Problem: TernaryCIFAR10Net forward, B=1024
//   conv3x3(3->64)+b+relu+pool   -> [B,64,16,16]
//   conv3x3(64->128)+b+relu+pool -> [B,128,8,8]
//   conv3x3(128->256)+b+relu+pool-> [B,256,4,4]
//   fc 4096->256 +b +relu
//   fc 256->10 +b
// All conv/fc weights are TWN-ternarized per tensor:
//   delta = 0.7*mean|w|; alpha = sum(|w|*mask)/max(sum(mask),1); wt = alpha*sign(w)*mask
// ---------------------------------------------------------------------------

#define NB 1024

// --------------------------- device scratch --------------------------------
__device__ float g_act1[NB * 64 * 16 * 16];   // pooled conv1 output
__device__ float g_act2[NB * 128 * 8 * 8];    // pooled conv2 output
__device__ float g_act3[NB * 256 * 4 * 4];    // pooled conv3 output == fc input
__device__ float g_fc1 [NB * 256];

__device__ float g_w1t[64 * 3 * 9];
__device__ float g_w2t[128 * 64 * 9];
__device__ float g_w3t[256 * 128 * 9];
__device__ float g_wf1t[256 * 4096];
__device__ float g_wf2t[10 * 256];

__device__ float g_part[5][64];
__device__ float g_cnt [5][64];
__device__ float g_delta[5];
__device__ float g_alpha[5];

__constant__ int c_n[5] = {64*3*9, 128*64*9, 256*128*9, 256*4096, 10*256};

__device__ __forceinline__ const float* pick_src(int t, const float* a, const float* b,
                                                 const float* c, const float* d, const float* e) {
    switch (t) { case 0: return a; case 1: return b; case 2: return c; case 3: return d; default: return e; }
}
__device__ __forceinline__ float* pick_dst(int t) {
    switch (t) { case 0: return g_w1t; case 1: return g_w2t; case 2: return g_w3t;
                 case 3: return g_wf1t; default: return g_wf2t; }
}

// --------------------------- ternarization ---------------------------------
__global__ void k_tstat1(const float* __restrict__ a, const float* __restrict__ b,
                         const float* __restrict__ c, const float* __restrict__ d,
                         const float* __restrict__ e) {
    int t = blockIdx.y;
    const float* w = pick_src(t, a, b, c, d, e);
    int n = c_n[t];
    float s = 0.f;
    for (int i = blockIdx.x * 256 + threadIdx.x; i < n; i += 64 * 256) s += fabsf(w[i]);
    __shared__ float sm[256];
    sm[threadIdx.x] = s; __syncthreads();
    for (int st = 128; st > 0; st >>= 1) {
        if (threadIdx.x < st) sm[threadIdx.x] += sm[threadIdx.x + st];
        __syncthreads();
    }
    if (threadIdx.x == 0) g_part[t][blockIdx.x] = sm[0];
}

__global__ void k_tfin1() {
    int t = blockIdx.x, tid = threadIdx.x;  // 64 threads
    __shared__ float sm[64];
    sm[tid] = g_part[t][tid]; __syncthreads();
    for (int st = 32; st > 0; st >>= 1) {
        if (tid < st) sm[tid] += sm[tid + st];
        __syncthreads();
    }
    if (tid == 0) g_delta[t] = 0.7f * sm[0] / (float)c_n[t];
}

__global__ void k_tstat2(const float* __restrict__ a, const float* __restrict__ b,
                         const float* __restrict__ c, const float* __restrict__ d,
                         const float* __restrict__ e) {
    int t = blockIdx.y;
    const float* w = pick_src(t, a, b, c, d, e);
    int n = c_n[t];
    float dlt = g_delta[t];
    float s = 0.f, cn = 0.f;
    for (int i = blockIdx.x * 256 + threadIdx.x; i < n; i += 64 * 256) {
        float av = fabsf(w[i]);
        if (av > dlt) { s += av; cn += 1.f; }
    }
    __shared__ float sm[256];
    __shared__ float sc[256];
    sm[threadIdx.x] = s; sc[threadIdx.x] = cn; __syncthreads();
    for (int st = 128; st > 0; st >>= 1) {
        if (threadIdx.x < st) { sm[threadIdx.x] += sm[threadIdx.x + st];
                                sc[threadIdx.x] += sc[threadIdx.x + st]; }
        __syncthreads();
    }
    if (threadIdx.x == 0) { g_part[t][blockIdx.x] = sm[0]; g_cnt[t][blockIdx.x] = sc[0]; }
}

__global__ void k_tfin2() {
    int t = blockIdx.x, tid = threadIdx.x;  // 64 threads
    __shared__ float sm[64];
    __shared__ float sc[64];
    sm[tid] = g_part[t][tid]; sc[tid] = g_cnt[t][tid]; __syncthreads();
    for (int st = 32; st > 0; st >>= 1) {
        if (tid < st) { sm[tid] += sm[tid + st]; sc[tid] += sc[tid + st]; }
        __syncthreads();
    }
    if (tid == 0) g_alpha[t] = sm[0] / fmaxf(sc[0], 1.f);
}

__global__ void k_twrite(const float* __restrict__ a, const float* __restrict__ b,
                         const float* __restrict__ c, const float* __restrict__ d,
                         const float* __restrict__ e) {
    int t = blockIdx.y;
    const float* w = pick_src(t, a, b, c, d, e);
    float* dst = pick_dst(t);
    int n = c_n[t];
    float dlt = g_delta[t], al = g_alpha[t];
    for (int i = blockIdx.x * 256 + threadIdx.x; i < n; i += 256 * 256) {
        float v = w[i];
        dst[i] = (fabsf(v) > dlt) ? copysignf(al, v) : 0.f;
    }
}

// --------------------------- conv1: 3->64, 32x32 -> pooled 16x16 ------------
__global__ void k_conv1(const float* __restrict__ x, const float* __restrict__ b1) {
    int n = blockIdx.x;
    __shared__ float sin[3][34][34];   // zero-padded image
    __shared__ float sw[64 * 27];
    int tid = threadIdx.x;  // 256

    for (int i = tid; i < 3 * 34 * 34; i += 256) {
        int c = i / 1156, r = i % 1156, y = r / 34, xx = r % 34;
        float v = 0.f;
        if (y >= 1 && y <= 32 && xx >= 1 && xx <= 32)
            v = x[((n * 3 + c) * 32 + (y - 1)) * 32 + (xx - 1)];
        sin[c][y][xx] = v;
    }
    for (int i = tid; i < 64 * 27; i += 256) sw[i] = g_w1t[i];
    __syncthreads();

    int ph = tid / 16, pw = tid % 16;
    // register-cache the 4x4 patch per channel (covers the 2x2 conv pixels)
    float p[3][4][4];
#pragma unroll
    for (int c = 0; c < 3; c++)
#pragma unroll
        for (int i = 0; i < 4; i++)
#pragma unroll
            for (int j = 0; j < 4; j++)
                p[c][i][j] = sin[c][2 * ph + i][2 * pw + j];

    for (int oc = 0; oc < 64; oc++) {
        const float* w = &sw[oc * 27];
        float mx = -3.0e38f;
#pragma unroll
        for (int dy = 0; dy < 2; dy++)
#pragma unroll
            for (int dx = 0; dx < 2; dx++) {
                float acc = 0.f;
#pragma unroll
                for (int c = 0; c < 3; c++)
#pragma unroll
                    for (int ky = 0; ky < 3; ky++)
#pragma unroll
                        for (int kx = 0; kx < 3; kx++)
                            acc += p[c][dy + ky][dx + kx] * w[c * 9 + ky * 3 + kx];
                mx = fmaxf(mx, acc);
            }
        float v = fmaxf(mx + b1[oc], 0.f);
        g_act1[((n * 64 + oc) * 16 + ph) * 16 + pw] = v;
    }
}

// --------------------------- conv2: 64->128, 16x16 -> pooled 8x8 ------------
__global__ void k_conv2(const float* __restrict__ b2) {
    int n = blockIdx.x, ocg = blockIdx.y;  // 8 groups of 16 oc
    int tid = threadIdx.x;                 // 256 = 16x16 conv pixels
    int y = tid / 16, xx = tid % 16;

    __shared__ float sin[18 * 18];
    __shared__ float sw[16 * 9];
    __shared__ float sstage[16 * 256];

    float acc[16];
#pragma unroll
    for (int o = 0; o < 16; o++) acc[o] = 0.f;

    for (int ic = 0; ic < 64; ic++) {
        for (int i = tid; i < 324; i += 256) {
            int ty = i / 18, tx = i % 18;
            float v = 0.f;
            if (ty >= 1 && ty <= 16 && tx >= 1 && tx <= 16)
                v = g_act1[((n * 64 + ic) * 16 + (ty - 1)) * 16 + (tx - 1)];
            sin[i] = v;
        }
        if (tid < 144) {
            int o = tid / 9, k = tid % 9;
            sw[tid] = g_w2t[(((ocg * 16 + o) * 64 + ic) * 9) + k];
        }
        __syncthreads();

        float r[9];
#pragma unroll
        for (int ky = 0; ky < 3; ky++)
#pragma unroll
            for (int kx = 0; kx < 3; kx++)
                r[ky * 3 + kx] = sin[(y + ky) * 18 + (xx + kx)];
#pragma unroll
        for (int o = 0; o < 16; o++) {
#pragma unroll
            for (int k = 0; k < 9; k++) acc[o] += r[k] * sw[o * 9 + k];
        }
        __syncthreads();
    }

#pragma unroll
    for (int o = 0; o < 16; o++) sstage[o * 256 + tid] = acc[o];
    __syncthreads();

    // 16 oc * 64 pooled = 1024 outputs, 4 per thread
    for (int p = 0; p < 4; p++) {
        int id = p * 256 + tid;
        int oc = id / 64, s = id % 64, py = s / 8, px = s % 8;
        int base = oc * 256 + (2 * py) * 16 + 2 * px;
        float v = fmaxf(fmaxf(sstage[base], sstage[base + 1]),
                        fmaxf(sstage[base + 16], sstage[base + 17]));
        v = fmaxf(v + b2[ocg * 16 + oc], 0.f);
        g_act2[((n * 128 + ocg * 16 + oc) * 8 + py) * 8 + px] = v;
    }
}

// --------------------------- conv3: 128->256, 8x8 -> pooled 4x4 -------------
__global__ void k_conv3(const float* __restrict__ b3) {
    int n = blockIdx.x, ocg = blockIdx.y;  // 16 groups of 16 oc
    int tid = threadIdx.x;                 // 256 = 64 pixels x 4 ic-slices
    int slice = tid >> 6;
    int px = tid & 63;
    int y = px >> 3, xx = px & 7;

    __shared__ float sin[4][100];
    __shared__ float sw[4][144];
    __shared__ float sstage[4][64][16];

    float acc[16];
#pragma unroll
    for (int o = 0; o < 16; o++) acc[o] = 0.f;

    for (int i = 0; i < 32; i++) {
        int ic = slice * 32 + i;
        for (int j = px; j < 100; j += 64) {
            int ty = j / 10, tx = j % 10;
            float v = 0.f;
            if (ty >= 1 && ty <= 8 && tx >= 1 && tx <= 8)
                v = g_act2[((n * 128 + ic) * 8 + (ty - 1)) * 8 + (tx - 1)];
            sin[slice][j] = v;
        }
        for (int j = px; j < 144; j += 64) {
            int o = j / 9, k = j % 9;
            sw[slice][j] = g_w3t[(((ocg * 16 + o) * 128 + ic) * 9) + k];
        }
        __syncthreads();

        float r[9];
#pragma unroll
        for (int ky = 0; ky < 3; ky++)
#pragma unroll
            for (int kx = 0; kx < 3; kx++)
                r[ky * 3 + kx] = sin[slice][(y + ky) * 10 + (xx + kx)];
#pragma unroll
        for (int o = 0; o < 16; o++) {
#pragma unroll
            for (int k = 0; k < 9; k++) acc[o] += r[k] * sw[slice][o * 9 + k];
        }
        __syncthreads();
    }

#pragma unroll
    for (int o = 0; o < 16; o++) sstage[slice][px][o] = acc[o];
    __syncthreads();

    // 16 oc * 16 pooled = 256 outputs, 1 per thread
    int oc = tid / 16, s = tid % 16, py = s / 4, pxx = s % 4;
    float mx = -3.0e38f;
#pragma unroll
    for (int dy = 0; dy < 2; dy++)
#pragma unroll
        for (int dx = 0; dx < 2; dx++) {
            int pid = (2 * py + dy) * 8 + (2 * pxx + dx);
            float v = sstage[0][pid][oc] + sstage[1][pid][oc] +
                      sstage[2][pid][oc] + sstage[3][pid][oc];
            mx = fmaxf(mx, v);
        }
    float out = fmaxf(mx + b3[ocg * 16 + oc], 0.f);
    g_act3[((n * 256 + ocg * 16 + oc) * 4 + py) * 4 + pxx] = out;
}

// --------------------------- fc1: [1024,4096] x [256,4096]^T + relu ---------
__global__ void k_fc1(const float* __restrict__ bf1) {
    __shared__ float sA[32][33];
    __shared__ float sB[32][33];
    int tid = threadIdx.x;
    int ty = tid / 16, tx = tid % 16;
    int m0 = blockIdx.x * 32, o0 = blockIdx.y * 32;
    float acc00 = 0.f, acc01 = 0.f, acc10 = 0.f, acc11 = 0.f;

    for (int k0 = 0; k0 < 4096; k0 += 32) {
        for (int i = tid; i < 1024; i += 256) {
            int r = i / 32, c = i % 32;
            sA[r][c] = g_act3[(m0 + r) * 4096 + k0 + c];
            sB[r][c] = g_wf1t[(o0 + r) * 4096 + k0 + c];
        }
        __syncthreads();
#pragma unroll
        for (int k = 0; k < 32; k++) {
            float a0 = sA[ty * 2][k], a1 = sA[ty * 2 + 1][k];
            float b0 = sB[tx * 2][k], b1 = sB[tx * 2 + 1][k];
            acc00 += a0 * b0; acc01 += a0 * b1;
            acc10 += a1 * b0; acc11 += a1 * b1;
        }
        __syncthreads();
    }
    int m = m0 + ty * 2, o = o0 + tx * 2;
    g_fc1[m * 256 + o]             = fmaxf(acc00 + bf1[o], 0.f);
    g_fc1[m * 256 + o + 1]         = fmaxf(acc01 + bf1[o + 1], 0.f);
    g_fc1[(m + 1) * 256 + o]       = fmaxf(acc10 + bf1[o], 0.f);
    g_fc1[(m + 1) * 256 + o + 1]   = fmaxf(acc11 + bf1[o + 1], 0.f);
}

// --------------------------- fc2: [1024,256] x [10,256]^T -------------------
__global__ void k_fc2(const float* __restrict__ bf2, float* __restrict__ out) {
    int i = blockIdx.x * blockDim.x + threadIdx.x;
    if (i >= NB * 10) return;
    int n = i / 10, o = i % 10;
    float s = bf2[o];
    const float* a = &g_fc1[n * 256];
    const float* w = &g_wf2t[o * 256];
#pragma unroll 8
    for (int k = 0; k < 256; k++) s += a[k] * w[k];
    out[i] = s;
}

// --------------------------- launch ----------------------------------------
extern "C" void kernel_launch(void* const* d_in, const int* in_sizes, int n_in,
                              void* d_out, int out_size) {
    const float* x   = (const float*)d_in[0];
    const float* w1  = (const float*)d_in[1];
    const float* b1  = (const float*)d_in[2];
    const float* w2  = (const float*)d_in[3];
    const float* b2  = (const float*)d_in[4];
    const float* w3  = (const float*)d_in[5];
    const float* b3  = (const float*)d_in[6];
    const float* wf1 = (const float*)d_in[7];
    const float* bf1 = (const float*)d_in[8];
    const float* wf2 = (const float*)d_in[9];
    const float* bf2 = (const float*)d_in[10];
    float* out = (float*)d_out;

    k_tstat1<<<dim3(64, 5), 256>>>(w1, w2, w3, wf1, wf2);
    k_tfin1<<<5, 64>>>();
    k_tstat2<<<dim3(64, 5), 256>>>(w1, w2, w3, wf1, wf2);
    k_tfin2<<<5, 64>>>();
    k_twrite<<<dim3(256, 5), 256>>>(w1, w2, w3, wf1, wf2);

    k_conv1<<<NB, 256>>>(x, b1);
    k_conv2<<<dim3(NB, 8), 256>>>(b2);
    k_conv3<<<dim3(NB, 16), 256>>>(b3);
    k_fc1<<<dim3(32, 8), 256>>>(bf1);
    k_fc2<<<(NB * 10 + 255) / 256, 256>>>(bf2, out);
}

// round 2
// speedup vs baseline: 1.1601x; 1.1601x over previous
#include <cuda_runtime.h>
#include <math.h>

// ---------------------------------------------------------------------------
// TernaryCIFAR10Net forward, B=1024 — fp32x2 (packed FFMA2) implementation.
// conv2/conv3 are implicit-GEMM with 8x8 FFMA2 register tiles; weights are
// ternarized + transposed to [ic][k][oc]; activations stored zero-padded.
// ---------------------------------------------------------------------------

#define NB 1024
typedef unsigned long long u64;

__device__ __forceinline__ u64 f2fma(u64 a, u64 b, u64 c) {
    u64 d; asm("fma.rn.f32x2 %0, %1, %2, %3;" : "=l"(d) : "l"(a), "l"(b), "l"(c)); return d;
}
__device__ __forceinline__ u64 fdup(float v) {
    u64 d; asm("mov.b64 %0, {%1, %1};" : "=l"(d) : "f"(v)); return d;
}
__device__ __forceinline__ float2 f2unpack(u64 d) {
    float2 r; asm("mov.b64 {%0, %1}, %2;" : "=f"(r.x), "=f"(r.y) : "l"(d)); return r;
}

// --------------------------- device scratch --------------------------------
__device__ float g_act1p[NB * 64 * 18 * 18];   // pooled conv1 out, zero-padded
__device__ float g_act2p[NB * 128 * 10 * 10];  // pooled conv2 out, zero-padded
__device__ float g_act3 [NB * 256 * 4 * 4];    // pooled conv3 out == fc input
__device__ float g_fc1p [4 * NB * 256];        // fc1 split-K partials
__device__ float g_fc1  [NB * 256];

__device__ float g_w1t[3 * 9 * 64];        // [c][k][oc]
__device__ float g_w2t[64 * 9 * 128];      // [ic][k][oc]
__device__ float g_w3t[128 * 9 * 256];     // [ic][k][oc]
__device__ float g_wf1t[4096 * 256];       // [k][oc]
__device__ float g_wf2t[10 * 256];         // [oc][k]

__device__ float g_part[5][64];
__device__ float g_cnt [5][64];
__device__ float g_delta[5];
__device__ float g_alpha[5];

__constant__ int c_n[5] = {64*3*9, 128*64*9, 256*128*9, 256*4096, 10*256};

__device__ __forceinline__ const float* pick_src(int t, const float* a, const float* b,
                                                 const float* c, const float* d, const float* e) {
    switch (t) { case 0: return a; case 1: return b; case 2: return c; case 3: return d; default: return e; }
}
__device__ __forceinline__ float* pick_dst(int t) {
    switch (t) { case 0: return g_w1t; case 1: return g_w2t; case 2: return g_w3t;
                 case 3: return g_wf1t; default: return g_wf2t; }
}

// --------------------------- ternarization ---------------------------------
__global__ void k_tstat1(const float* __restrict__ a, const float* __restrict__ b,
                         const float* __restrict__ c, const float* __restrict__ d,
                         const float* __restrict__ e) {
    int t = blockIdx.y;
    const float* w = pick_src(t, a, b, c, d, e);
    int n = c_n[t];
    float s = 0.f;
    for (int i = blockIdx.x * 256 + threadIdx.x; i < n; i += 64 * 256) s += fabsf(w[i]);
    __shared__ float sm[256];
    sm[threadIdx.x] = s; __syncthreads();
    for (int st = 128; st > 0; st >>= 1) {
        if (threadIdx.x < st) sm[threadIdx.x] += sm[threadIdx.x + st];
        __syncthreads();
    }
    if (threadIdx.x == 0) g_part[t][blockIdx.x] = sm[0];
}

__global__ void k_tfin1() {
    int t = blockIdx.x, tid = threadIdx.x;
    __shared__ float sm[64];
    sm[tid] = g_part[t][tid]; __syncthreads();
    for (int st = 32; st > 0; st >>= 1) {
        if (tid < st) sm[tid] += sm[tid + st];
        __syncthreads();
    }
    if (tid == 0) g_delta[t] = 0.7f * sm[0] / (float)c_n[t];
}

__global__ void k_tstat2(const float* __restrict__ a, const float* __restrict__ b,
                         const float* __restrict__ c, const float* __restrict__ d,
                         const float* __restrict__ e) {
    int t = blockIdx.y;
    const float* w = pick_src(t, a, b, c, d, e);
    int n = c_n[t];
    float dlt = g_delta[t];
    float s = 0.f, cn = 0.f;
    for (int i = blockIdx.x * 256 + threadIdx.x; i < n; i += 64 * 256) {
        float av = fabsf(w[i]);
        if (av > dlt) { s += av; cn += 1.f; }
    }
    __shared__ float sm[256];
    __shared__ float sc[256];
    sm[threadIdx.x] = s; sc[threadIdx.x] = cn; __syncthreads();
    for (int st = 128; st > 0; st >>= 1) {
        if (threadIdx.x < st) { sm[threadIdx.x] += sm[threadIdx.x + st];
                                sc[threadIdx.x] += sc[threadIdx.x + st]; }
        __syncthreads();
    }
    if (threadIdx.x == 0) { g_part[t][blockIdx.x] = sm[0]; g_cnt[t][blockIdx.x] = sc[0]; }
}

__global__ void k_tfin2() {
    int t = blockIdx.x, tid = threadIdx.x;
    __shared__ float sm[64];
    __shared__ float sc[64];
    sm[tid] = g_part[t][tid]; sc[tid] = g_cnt[t][tid]; __syncthreads();
    for (int st = 32; st > 0; st >>= 1) {
        if (tid < st) { sm[tid] += sm[tid + st]; sc[tid] += sc[tid + st]; }
        __syncthreads();
    }
    if (tid == 0) g_alpha[t] = sm[0] / fmaxf(sc[0], 1.f);
}

// write ternarized weights, transposing conv/fc layouts for the GEMM kernels
__global__ void k_twrite(const float* __restrict__ a, const float* __restrict__ b,
                         const float* __restrict__ c, const float* __restrict__ d,
                         const float* __restrict__ e) {
    int t = blockIdx.y;
    const float* w = pick_src(t, a, b, c, d, e);
    float* dst = pick_dst(t);
    int n = c_n[t];
    float dlt = g_delta[t], al = g_alpha[t];
    for (int i = blockIdx.x * 256 + threadIdx.x; i < n; i += 256 * 256) {
        float v = w[i];
        float o = (fabsf(v) > dlt) ? copysignf(al, v) : 0.f;
        int dI;
        switch (t) {
            case 0: { int oc = i / 27,   r = i % 27;   dI = r * 64  + oc; break; }
            case 1: { int oc = i / 576,  r = i % 576;  dI = r * 128 + oc; break; }
            case 2: { int oc = i / 1152, r = i % 1152; dI = r * 256 + oc; break; }
            case 3: { int oo = i >> 12,  k = i & 4095; dI = k * 256 + oo; break; }
            default: dI = i;
        }
        dst[dI] = o;
    }
}

// --------------------------- conv1: 3->64 ----------------------------------
__global__ __launch_bounds__(256, 1) void k_conv1(const float* __restrict__ x,
                                                  const float* __restrict__ b1) {
    int n = blockIdx.x, tid = threadIdx.x;
    __shared__ float sin1[3 * 34 * 34];
    __shared__ float sw[27 * 64];
    __shared__ float sb[64];

    for (int i = tid; i < 3 * 34 * 34; i += 256) {
        int c = i / 1156, r = i % 1156, y = r / 34, xx = r % 34;
        float v = 0.f;
        if (y >= 1 && y <= 32 && xx >= 1 && xx <= 32)
            v = x[((n * 3 + c) * 32 + (y - 1)) * 32 + (xx - 1)];
        sin1[i] = v;
    }
    for (int i = tid; i < 27 * 64; i += 256) sw[i] = g_w1t[i];
    if (tid < 64) sb[tid] = b1[tid];
    // zero the 18x18 borders of act1p for this image
    for (int i = tid; i < 64 * 68; i += 256) {
        int ch = i / 68, bb = i % 68, y, xx;
        if (bb < 18)      { y = 0;  xx = bb; }
        else if (bb < 36) { y = 17; xx = bb - 18; }
        else { int r = bb - 36; y = 1 + (r >> 1); xx = (r & 1) * 17; }
        g_act1p[(n * 64 + ch) * 324 + y * 18 + xx] = 0.f;
    }
    __syncthreads();

    int ph = tid >> 4, pw = tid & 15;
    u64 pd[3][4][4];
#pragma unroll
    for (int c = 0; c < 3; c++)
#pragma unroll
        for (int i = 0; i < 4; i++)
#pragma unroll
            for (int j = 0; j < 4; j++)
                pd[c][i][j] = fdup(sin1[c * 1156 + (2 * ph + i) * 34 + (2 * pw + j)]);

    for (int op = 0; op < 32; op++) {
        u64 a0 = 0, a1 = 0, a2 = 0, a3 = 0;
#pragma unroll
        for (int c = 0; c < 3; c++)
#pragma unroll
            for (int ky = 0; ky < 3; ky++)
#pragma unroll
                for (int kx = 0; kx < 3; kx++) {
                    u64 bw = *(const u64*)&sw[(c * 9 + ky * 3 + kx) * 64 + op * 2];
                    a0 = f2fma(pd[c][ky][kx],         bw, a0);
                    a1 = f2fma(pd[c][ky][kx + 1],     bw, a1);
                    a2 = f2fma(pd[c][ky + 1][kx],     bw, a2);
                    a3 = f2fma(pd[c][ky + 1][kx + 1], bw, a3);
                }
        float2 v0 = f2unpack(a0), v1 = f2unpack(a1), v2 = f2unpack(a2), v3 = f2unpack(a3);
        float lo = fmaxf(fmaxf(v0.x, v1.x), fmaxf(v2.x, v3.x));
        float hi = fmaxf(fmaxf(v0.y, v1.y), fmaxf(v2.y, v3.y));
        int oc = op * 2;
        g_act1p[((n * 64 + oc)     * 18 + ph + 1) * 18 + pw + 1] = fmaxf(lo + sb[oc],     0.f);
        g_act1p[((n * 64 + oc + 1) * 18 + ph + 1) * 18 + pw + 1] = fmaxf(hi + sb[oc + 1], 0.f);
    }
}

// --------------------------- conv2: 64->128 --------------------------------
__global__ __launch_bounds__(256, 1) void k_conv2(const float* __restrict__ b2) {
    int n = blockIdx.x, tid = threadIdx.x;
    __shared__ float sin2[2 * 324];
    __shared__ float sw2[2 * 9 * 128];
    __shared__ float sst[32 * 256];
    __shared__ float sb[128];

    if (tid < 128) sb[tid] = b2[tid];
    // zero the 10x10 borders of act2p for this image
    for (int i = tid; i < 128 * 36; i += 256) {
        int ch = i / 36, bb = i % 36, y, xx;
        if (bb < 10)      { y = 0; xx = bb; }
        else if (bb < 20) { y = 9; xx = bb - 10; }
        else { int r = bb - 20; y = 1 + (r >> 1); xx = (r & 1) * 9; }
        g_act2p[(n * 128 + ch) * 100 + y * 10 + xx] = 0.f;
    }

    int mt = tid >> 3, nt = tid & 7;
    int y = mt >> 1, x0 = (mt & 1) * 8, oc0 = nt * 16;

    u64 acc[8][8];
#pragma unroll
    for (int i = 0; i < 8; i++)
#pragma unroll
        for (int j = 0; j < 8; j++) acc[i][j] = 0ull;

    const float* a1b = &g_act1p[n * 64 * 324];
    for (int ic2 = 0; ic2 < 32; ic2++) {
        __syncthreads();
        for (int i = tid; i < 648; i += 256)  sin2[i] = a1b[ic2 * 648 + i];
        for (int i = tid; i < 2304; i += 256) sw2[i]  = g_w2t[ic2 * 2304 + i];
        __syncthreads();

        for (int icl = 0; icl < 2; icl++) {
            const float* S = &sin2[icl * 324];
            const float* W = &sw2[icl * 1152];
#pragma unroll
            for (int ky = 0; ky < 3; ky++)
#pragma unroll
                for (int kx = 0; kx < 3; kx++) {
                    int k = ky * 3 + kx;
                    u64 bf[8];
#pragma unroll
                    for (int j = 0; j < 8; j++)
                        bf[j] = *(const u64*)&W[k * 128 + oc0 + 2 * j];
                    const float* ap = &S[(y + ky) * 18 + x0 + kx];
                    u64 ad[8];
#pragma unroll
                    for (int i = 0; i < 8; i++) ad[i] = fdup(ap[i]);
#pragma unroll
                    for (int i = 0; i < 8; i++)
#pragma unroll
                        for (int j = 0; j < 8; j++)
                            acc[i][j] = f2fma(ad[i], bf[j], acc[i][j]);
                }
        }
    }

    // pool+bias+relu in 4 chunks of 32 oc
    for (int c = 0; c < 4; c++) {
        __syncthreads();
        if ((nt >> 1) == c) {
#pragma unroll
            for (int j = 0; j < 8; j++) {
                int ocl = oc0 + 2 * j - 32 * c;
#pragma unroll
                for (int i = 0; i < 8; i++) {
                    float2 v = f2unpack(acc[i][j]);
                    int px = y * 16 + x0 + i;
                    sst[ocl * 256 + px]       = v.x;
                    sst[(ocl + 1) * 256 + px] = v.y;
                }
            }
        }
        __syncthreads();
        for (int q = 0; q < 8; q++) {
            int id = tid * 8 + q;
            int ocl = id >> 6, s = id & 63, py = s >> 3, px = s & 7;
            int b0 = ocl * 256 + 2 * py * 16 + 2 * px;
            float v = fmaxf(fmaxf(sst[b0], sst[b0 + 1]), fmaxf(sst[b0 + 16], sst[b0 + 17]));
            int oc = c * 32 + ocl;
            g_act2p[(n * 128 + oc) * 100 + (py + 1) * 10 + px + 1] = fmaxf(v + sb[oc], 0.f);
        }
    }
}

// --------------------------- conv3: 128->256 -------------------------------
__global__ __launch_bounds__(256, 1) void k_conv3(const float* __restrict__ b3) {
    int n0 = blockIdx.x * 2, tid = threadIdx.x;
    __shared__ float sin3[2 * 2 * 100];
    __shared__ float sw3[2 * 9 * 256];
    __shared__ float sst[2 * 32 * 64];
    __shared__ float sb[256];

    if (tid < 256) sb[tid] = b3[tid];

    int mt = tid >> 4, nt = tid & 15;
    int img = mt >> 3, y = mt & 7, oc0 = nt * 16;

    u64 acc[8][8];
#pragma unroll
    for (int i = 0; i < 8; i++)
#pragma unroll
        for (int j = 0; j < 8; j++) acc[i][j] = 0ull;

    for (int ic2 = 0; ic2 < 64; ic2++) {
        __syncthreads();
        for (int i = tid; i < 400; i += 256) {
            int im = i / 200, icl = (i / 100) & 1, j = i % 100;
            sin3[i] = g_act2p[((n0 + im) * 128 + ic2 * 2 + icl) * 100 + j];
        }
        for (int i = tid; i < 4608; i += 256) sw3[i] = g_w3t[ic2 * 4608 + i];
        __syncthreads();

        for (int icl = 0; icl < 2; icl++) {
            const float* S = &sin3[img * 200 + icl * 100];
            const float* W = &sw3[icl * 2304];
#pragma unroll
            for (int ky = 0; ky < 3; ky++)
#pragma unroll
                for (int kx = 0; kx < 3; kx++) {
                    int k = ky * 3 + kx;
                    u64 bf[8];
#pragma unroll
                    for (int j = 0; j < 8; j++)
                        bf[j] = *(const u64*)&W[k * 256 + oc0 + 2 * j];
                    const float* ap = &S[(y + ky) * 10 + kx];
                    u64 ad[8];
#pragma unroll
                    for (int i = 0; i < 8; i++) ad[i] = fdup(ap[i]);
#pragma unroll
                    for (int i = 0; i < 8; i++)
#pragma unroll
                        for (int j = 0; j < 8; j++)
                            acc[i][j] = f2fma(ad[i], bf[j], acc[i][j]);
                }
        }
    }

    // pool+bias+relu in 8 chunks of 32 oc
    for (int c = 0; c < 8; c++) {
        __syncthreads();
        if ((nt >> 1) == c) {
#pragma unroll
            for (int j = 0; j < 8; j++) {
                int ocl = oc0 + 2 * j - 32 * c;
#pragma unroll
                for (int i = 0; i < 8; i++) {
                    float2 v = f2unpack(acc[i][j]);
                    int base = img * 2048 + y * 8 + i;
                    sst[base + ocl * 64]       = v.x;
                    sst[base + (ocl + 1) * 64] = v.y;
                }
            }
        }
        __syncthreads();
        for (int q = 0; q < 4; q++) {
            int id = tid * 4 + q;
            int im = id >> 9, rest = id & 511;
            int ocl = rest >> 4, s = rest & 15, py = s >> 2, px = s & 3;
            int b0 = im * 2048 + ocl * 64 + 2 * py * 8 + 2 * px;
            float v = fmaxf(fmaxf(sst[b0], sst[b0 + 1]), fmaxf(sst[b0 + 8], sst[b0 + 9]));
            int oc = c * 32 + ocl;
            g_act3[((n0 + im) * 256 + oc) * 16 + py * 4 + px] = fmaxf(v + sb[oc], 0.f);
        }
    }
}

// --------------------------- fc1 split-K GEMM ------------------------------
__global__ __launch_bounds__(256, 1) void k_fc1() {
    __shared__ float sA[64][33];
    __shared__ float sB[32][66];
    int tid = threadIdx.x;
    int tm = tid >> 4, tn = tid & 15;
    int m0 = blockIdx.x * 64, o0 = blockIdx.y * 64, ks = blockIdx.z;
    int kbase = ks * 1024;

    u64 acc[4][2];
#pragma unroll
    for (int i = 0; i < 4; i++) { acc[i][0] = 0ull; acc[i][1] = 0ull; }

    for (int kt = 0; kt < 32; kt++) {
        int k0 = kbase + kt * 32;
        __syncthreads();
        for (int i = tid; i < 2048; i += 256) {
            int r = i >> 5, cc = i & 31;
            sA[r][cc] = g_act3[(m0 + r) * 4096 + k0 + cc];
        }
        for (int i = tid; i < 2048; i += 256) {
            int r = i >> 6, cc = i & 63;
            sB[r][cc] = g_wf1t[(k0 + r) * 256 + o0 + cc];
        }
        __syncthreads();
#pragma unroll
        for (int k = 0; k < 32; k++) {
            u64 b0 = *(const u64*)&sB[k][tn * 4];
            u64 b1 = *(const u64*)&sB[k][tn * 4 + 2];
#pragma unroll
            for (int i = 0; i < 4; i++) {
                u64 a = fdup(sA[tm * 4 + i][k]);
                acc[i][0] = f2fma(a, b0, acc[i][0]);
                acc[i][1] = f2fma(a, b1, acc[i][1]);
            }
        }
    }
    float* dst = &g_fc1p[ks * NB * 256];
#pragma unroll
    for (int i = 0; i < 4; i++) {
        float2 v0 = f2unpack(acc[i][0]);
        float2 v1 = f2unpack(acc[i][1]);
        int row = (m0 + tm * 4 + i) * 256 + o0 + tn * 4;
        dst[row]     = v0.x; dst[row + 1] = v0.y;
        dst[row + 2] = v1.x; dst[row + 3] = v1.y;
    }
}

__global__ void k_fc1red(const float* __restrict__ bf1) {
    int i = blockIdx.x * 256 + threadIdx.x;   // 1024*256 elems
    int o = i & 255;
    float v = g_fc1p[i] + g_fc1p[NB * 256 + i] + g_fc1p[2 * NB * 256 + i] + g_fc1p[3 * NB * 256 + i];
    g_fc1[i] = fmaxf(v + bf1[o], 0.f);
}

// --------------------------- fc2 -------------------------------------------
__global__ void k_fc2(const float* __restrict__ bf2, float* __restrict__ out) {
    int i = blockIdx.x * blockDim.x + threadIdx.x;
    if (i >= NB * 10) return;
    int n = i / 10, o = i % 10;
    float s = bf2[o];
    const float* a = &g_fc1[n * 256];
    const float* w = &g_wf2t[o * 256];
#pragma unroll 8
    for (int k = 0; k < 256; k++) s += a[k] * w[k];
    out[i] = s;
}

// --------------------------- launch ----------------------------------------
extern "C" void kernel_launch(void* const* d_in, const int* in_sizes, int n_in,
                              void* d_out, int out_size) {
    const float* x   = (const float*)d_in[0];
    const float* w1  = (const float*)d_in[1];
    const float* b1  = (const float*)d_in[2];
    const float* w2  = (const float*)d_in[3];
    const float* b2  = (const float*)d_in[4];
    const float* w3  = (const float*)d_in[5];
    const float* b3  = (const float*)d_in[6];
    const float* wf1 = (const float*)d_in[7];
    const float* bf1 = (const float*)d_in[8];
    const float* wf2 = (const float*)d_in[9];
    const float* bf2 = (const float*)d_in[10];
    float* out = (float*)d_out;

    k_tstat1<<<dim3(64, 5), 256>>>(w1, w2, w3, wf1, wf2);
    k_tfin1<<<5, 64>>>();
    k_tstat2<<<dim3(64, 5), 256>>>(w1, w2, w3, wf1, wf2);
    k_tfin2<<<5, 64>>>();
    k_twrite<<<dim3(256, 5), 256>>>(w1, w2, w3, wf1, wf2);

    k_conv1<<<NB, 256>>>(x, b1);
    k_conv2<<<NB, 256>>>(b2);
    k_conv3<<<NB / 2, 256>>>(b3);
    k_fc1<<<dim3(16, 4, 4), 256>>>();
    k_fc1red<<<NB, 256>>>(bf1);
    k_fc2<<<(NB * 10 + 255) / 256, 256>>>(bf2, out);
}

// round 4
// speedup vs baseline: 5.4497x; 4.6976x over previous
#include <cuda_runtime.h>
#include <cuda_bf16.h>
#include <math.h>
#include <stdint.h>

// ---------------------------------------------------------------------------
// TernaryCIFAR10Net forward, B=1024 — mma.sync (HMMA) bf16 split-precision.
//   weights: ternarized sign (+-1/0) bf16, alpha folded into fp32 epilogue.
//   activations: x = hi + lo bf16 planes, both accumulated into fp32 -> ~fp32.
// ---------------------------------------------------------------------------

#define NB 1024
typedef unsigned long long u64;
typedef __nv_bfloat16 bf16;

__device__ __forceinline__ uint32_t smem_u32(const void* p) {
    uint32_t a;
    asm("{ .reg .u64 t; cvta.to.shared.u64 t, %1; cvt.u32.u64 %0, t; }" : "=r"(a) : "l"(p));
    return a;
}
__device__ __forceinline__ void ldsm4(uint32_t addr, uint32_t& r0, uint32_t& r1,
                                      uint32_t& r2, uint32_t& r3) {
    asm volatile("ldmatrix.sync.aligned.m8n8.x4.shared.b16 {%0,%1,%2,%3}, [%4];"
                 : "=r"(r0), "=r"(r1), "=r"(r2), "=r"(r3) : "r"(addr));
}
__device__ __forceinline__ void mma16816(float* d, uint32_t a0, uint32_t a1, uint32_t a2,
                                         uint32_t a3, uint32_t b0, uint32_t b1) {
    asm volatile("mma.sync.aligned.m16n8k16.row.col.f32.bf16.bf16.f32 "
                 "{%0,%1,%2,%3}, {%4,%5,%6,%7}, {%8,%9}, {%0,%1,%2,%3};"
                 : "+f"(d[0]), "+f"(d[1]), "+f"(d[2]), "+f"(d[3])
                 : "r"(a0), "r"(a1), "r"(a2), "r"(a3), "r"(b0), "r"(b1));
}
// fp32x2 helpers for conv1
__device__ __forceinline__ u64 f2fma(u64 a, u64 b, u64 c) {
    u64 d; asm("fma.rn.f32x2 %0, %1, %2, %3;" : "=l"(d) : "l"(a), "l"(b), "l"(c)); return d;
}
__device__ __forceinline__ u64 fdup(float v) {
    u64 d; asm("mov.b64 %0, {%1, %1};" : "=l"(d) : "f"(v)); return d;
}
__device__ __forceinline__ float2 f2unpack(u64 d) {
    float2 r; asm("mov.b64 {%0, %1}, %2;" : "=f"(r.x), "=f"(r.y) : "l"(d)); return r;
}

// ========================= device scratch ===================================
#define A1SZ (NB * 18 * 18 * 64)
#define A2SZ (NB * 10 * 10 * 128)
__device__ __align__(16) bf16 g_acts[2 * (A1SZ + A2SZ)];
#define G_A1H (g_acts)
#define G_A1L (g_acts + A1SZ)
#define G_A2H (g_acts + 2 * A1SZ)
#define G_A2L (g_acts + 2 * A1SZ + A2SZ)

__device__ __align__(16) bf16 g_act3h[NB * 16 * 256];   // [n][s][c]
__device__ __align__(16) bf16 g_act3l[NB * 16 * 256];
__device__ float g_fc1p[8 * NB * 256];
__device__ float g_fc1[NB * 256];

__device__ float g_w1t[27 * 64];                    // fp32 sign [k][oc]
__device__ __align__(16) bf16 g_w2s[9 * 128 * 64];  // sign [tap][oc][ic]
__device__ __align__(16) bf16 g_w3s[9 * 256 * 128]; // sign [tap][oc][ic]
__device__ __align__(16) bf16 g_wf1s[256 * 4096];   // sign [o][k'], k'=s*256+c
__device__ float g_wf2t[10 * 256];

__device__ float g_part[5][64];
__device__ float g_cnt[5][64];
__device__ float g_delta[5];
__device__ float g_alpha[5];

__constant__ int c_n[5] = {64 * 3 * 9, 128 * 64 * 9, 256 * 128 * 9, 256 * 4096, 10 * 256};

__device__ __forceinline__ const float* pick_src(int t, const float* a, const float* b,
                                                 const float* c, const float* d, const float* e) {
    switch (t) { case 0: return a; case 1: return b; case 2: return c; case 3: return d; default: return e; }
}

// ========================= ternarization ====================================
__global__ void k_tstat1(const float* __restrict__ a, const float* __restrict__ b,
                         const float* __restrict__ c, const float* __restrict__ d,
                         const float* __restrict__ e) {
    int t = blockIdx.y;
    const float* w = pick_src(t, a, b, c, d, e);
    int n = c_n[t];
    float s = 0.f;
    for (int i = blockIdx.x * 256 + threadIdx.x; i < n; i += 64 * 256) s += fabsf(w[i]);
    __shared__ float sm[256];
    sm[threadIdx.x] = s; __syncthreads();
    for (int st = 128; st > 0; st >>= 1) {
        if (threadIdx.x < st) sm[threadIdx.x] += sm[threadIdx.x + st];
        __syncthreads();
    }
    if (threadIdx.x == 0) g_part[t][blockIdx.x] = sm[0];
}
__global__ void k_tfin1() {
    int t = blockIdx.x, tid = threadIdx.x;
    __shared__ float sm[64];
    sm[tid] = g_part[t][tid]; __syncthreads();
    for (int st = 32; st > 0; st >>= 1) {
        if (tid < st) sm[tid] += sm[tid + st];
        __syncthreads();
    }
    if (tid == 0) g_delta[t] = 0.7f * sm[0] / (float)c_n[t];
}
__global__ void k_tstat2(const float* __restrict__ a, const float* __restrict__ b,
                         const float* __restrict__ c, const float* __restrict__ d,
                         const float* __restrict__ e) {
    int t = blockIdx.y;
    const float* w = pick_src(t, a, b, c, d, e);
    int n = c_n[t];
    float dlt = g_delta[t];
    float s = 0.f, cn = 0.f;
    for (int i = blockIdx.x * 256 + threadIdx.x; i < n; i += 64 * 256) {
        float av = fabsf(w[i]);
        if (av > dlt) { s += av; cn += 1.f; }
    }
    __shared__ float sm[256], sc[256];
    sm[threadIdx.x] = s; sc[threadIdx.x] = cn; __syncthreads();
    for (int st = 128; st > 0; st >>= 1) {
        if (threadIdx.x < st) { sm[threadIdx.x] += sm[threadIdx.x + st]; sc[threadIdx.x] += sc[threadIdx.x + st]; }
        __syncthreads();
    }
    if (threadIdx.x == 0) { g_part[t][blockIdx.x] = sm[0]; g_cnt[t][blockIdx.x] = sc[0]; }
}
__global__ void k_tfin2() {
    int t = blockIdx.x, tid = threadIdx.x;
    __shared__ float sm[64], sc[64];
    sm[tid] = g_part[t][tid]; sc[tid] = g_cnt[t][tid]; __syncthreads();
    for (int st = 32; st > 0; st >>= 1) {
        if (tid < st) { sm[tid] += sm[tid + st]; sc[tid] += sc[tid + st]; }
        __syncthreads();
    }
    if (tid == 0) g_alpha[t] = sm[0] / fmaxf(sc[0], 1.f);
}
__global__ void k_twrite(const float* __restrict__ a, const float* __restrict__ b,
                         const float* __restrict__ c, const float* __restrict__ d,
                         const float* __restrict__ e) {
    int t = blockIdx.y;
    const float* w = pick_src(t, a, b, c, d, e);
    int n = c_n[t];
    float dlt = g_delta[t];
    for (int i = blockIdx.x * 256 + threadIdx.x; i < n; i += 256 * 256) {
        float v = w[i];
        float s = (fabsf(v) > dlt) ? (v > 0.f ? 1.f : -1.f) : 0.f;
        switch (t) {
            case 0: { int oc = i / 27,   r = i % 27;  g_w1t[r * 64 + oc] = s; } break;
            case 1: { int oc = i / 576,  r = i % 576;  int ic = r / 9, k = r % 9;
                      g_w2s[(k * 128 + oc) * 64 + ic]  = __float2bfloat16(s); } break;
            case 2: { int oc = i / 1152, r = i % 1152; int ic = r / 9, k = r % 9;
                      g_w3s[(k * 256 + oc) * 128 + ic] = __float2bfloat16(s); } break;
            case 3: { int o = i >> 12, k = i & 4095; int ch = k >> 4, s4 = k & 15;
                      g_wf1s[o * 4096 + s4 * 256 + ch] = __float2bfloat16(s); } break;
            default: g_wf2t[i] = s;
        }
    }
}

// ========================= zero padded activation buffers ==================
__global__ void k_zero() {
    u64* p = (u64*)g_acts;
    const long nw = (long)(2 * (A1SZ + A2SZ)) / 4;
    for (long i = (long)blockIdx.x * 256 + threadIdx.x; i < nw; i += (long)gridDim.x * 256) p[i] = 0;
}

// ========================= conv1: 3->64 (FFMA2) =============================
__global__ __launch_bounds__(256) void k_conv1(const float* __restrict__ x,
                                               const float* __restrict__ b1) {
    int n = blockIdx.x, tid = threadIdx.x;
    __shared__ float sin1[3 * 34 * 34];
    __shared__ float sw[27 * 64];
    __shared__ float sb[64];
    __shared__ float sal;

    for (int i = tid; i < 3 * 34 * 34; i += 256) {
        int c = i / 1156, r = i % 1156, y = r / 34, xx = r % 34;
        float v = 0.f;
        if (y >= 1 && y <= 32 && xx >= 1 && xx <= 32)
            v = x[((n * 3 + c) * 32 + (y - 1)) * 32 + (xx - 1)];
        sin1[i] = v;
    }
    for (int i = tid; i < 27 * 64; i += 256) sw[i] = g_w1t[i];
    if (tid < 64) sb[tid] = b1[tid];
    if (tid == 0) sal = g_alpha[0];
    __syncthreads();

    int ph = tid >> 4, pw = tid & 15;
    float p[3][4][4];
#pragma unroll
    for (int c = 0; c < 3; c++)
#pragma unroll
        for (int i = 0; i < 4; i++)
#pragma unroll
            for (int j = 0; j < 4; j++)
                p[c][i][j] = sin1[c * 1156 + (2 * ph + i) * 34 + (2 * pw + j)];
    float alpha = sal;
    int obase = ((n * 18 + ph + 1) * 18 + (pw + 1)) * 64;

    for (int g = 0; g < 8; g++) {
        u64 acc[4][4];
#pragma unroll
        for (int i = 0; i < 4; i++)
#pragma unroll
            for (int j = 0; j < 4; j++) acc[i][j] = 0ull;
#pragma unroll
        for (int c = 0; c < 3; c++)
#pragma unroll
            for (int ky = 0; ky < 3; ky++)
#pragma unroll
                for (int kx = 0; kx < 3; kx++) {
                    int k = c * 9 + ky * 3 + kx;
                    u64 a00 = fdup(p[c][ky][kx]),     a01 = fdup(p[c][ky][kx + 1]);
                    u64 a10 = fdup(p[c][ky + 1][kx]), a11 = fdup(p[c][ky + 1][kx + 1]);
#pragma unroll
                    for (int pr = 0; pr < 4; pr++) {
                        u64 bw = *(const u64*)&sw[k * 64 + g * 8 + pr * 2];
                        acc[pr][0] = f2fma(a00, bw, acc[pr][0]);
                        acc[pr][1] = f2fma(a01, bw, acc[pr][1]);
                        acc[pr][2] = f2fma(a10, bw, acc[pr][2]);
                        acc[pr][3] = f2fma(a11, bw, acc[pr][3]);
                    }
                }
        unsigned short hh[8], ll[8];
#pragma unroll
        for (int pr = 0; pr < 4; pr++) {
            float2 v0 = f2unpack(acc[pr][0]), v1 = f2unpack(acc[pr][1]);
            float2 v2 = f2unpack(acc[pr][2]), v3 = f2unpack(acc[pr][3]);
            float lo = fmaxf(fmaxf(v0.x, v1.x), fmaxf(v2.x, v3.x));
            float hi = fmaxf(fmaxf(v0.y, v1.y), fmaxf(v2.y, v3.y));
            float vl = fmaxf(alpha * lo + sb[g * 8 + pr * 2],     0.f);
            float vh = fmaxf(alpha * hi + sb[g * 8 + pr * 2 + 1], 0.f);
            bf16 h0 = __float2bfloat16(vl); bf16 l0 = __float2bfloat16(vl - __bfloat162float(h0));
            bf16 h1 = __float2bfloat16(vh); bf16 l1 = __float2bfloat16(vh - __bfloat162float(h1));
            hh[pr * 2] = __bfloat16_as_ushort(h0); hh[pr * 2 + 1] = __bfloat16_as_ushort(h1);
            ll[pr * 2] = __bfloat16_as_ushort(l0); ll[pr * 2 + 1] = __bfloat16_as_ushort(l1);
        }
        *(uint4*)(G_A1H + obase + g * 8) = *(uint4*)hh;
        *(uint4*)(G_A1L + obase + g * 8) = *(uint4*)ll;
    }
}

// ========================= conv2: 64->128 (mma.sync) ========================
// CTA = half image (128 M-rows), N=128 oc, 256 threads (8 warps, warp=16x128).
// M-row m <-> pixel: b=m>>2 (pool block), c=m&3 (corner);
//   y = h*8 + (b>>3)*2 + (c>>1), x = (b&7)*2 + (c&1)
#define STR 72
#define SA_H 0
#define SA_L (128 * STR * 2)
#define SB_OFF (2 * 128 * STR * 2)
#define SBIAS (3 * 128 * STR * 2)
#define C2_SMEM (SBIAS + 512 + 16)
__global__ __launch_bounds__(256, 2) void k_conv2m(const float* __restrict__ b2) {
    extern __shared__ __align__(16) char smem[];
    uint32_t sbase = smem_u32(smem);
    float* sbias = (float*)(smem + SBIAS);
    int tid = threadIdx.x, wid = tid >> 5, lane = tid & 31;
    int n = blockIdx.x >> 1, h = blockIdx.x & 1;
    if (tid < 128) sbias[tid] = b2[tid];

    // A staging assignment: thread -> (row mrow, plane)
    int mrow = tid >> 1, plane = tid & 1;
    {
        // nothing
    }
    int bblk = mrow >> 2, corn = mrow & 3;
    int ay = h * 8 + (bblk >> 3) * 2 + (corn >> 1);
    int ax = (bblk & 7) * 2 + (corn & 1);
    const bf16* aplane = plane ? G_A1L : G_A1H;
    bf16* sArow = (bf16*)(smem + (plane ? SA_L : SA_H)) + mrow * STR;
    // B staging: (row brow, half)
    int brow = tid >> 1, bhalf = tid & 1;
    bf16* sBrow = (bf16*)(smem + SB_OFF) + brow * STR + bhalf * 32;

    float acc[16][4];
#pragma unroll
    for (int i = 0; i < 16; i++)
#pragma unroll
        for (int j = 0; j < 4; j++) acc[i][j] = 0.f;

    // per-lane ldmatrix offsets
    int arow_l = wid * 16 + (lane & 15);
    int khalf = ((lane >> 4) & 1) * 8;
    uint32_t aAddrH = sbase + SA_H + (uint32_t)(arow_l * STR + khalf) * 2;
    uint32_t aAddrL = sbase + SA_L + (uint32_t)(arow_l * STR + khalf) * 2;
    uint32_t bAddr0 = sbase + SB_OFF + (uint32_t)((lane & 15) * STR + khalf) * 2;

    for (int tap = 0; tap < 9; tap++) {
        int ky = tap / 3, kx = tap - ky * 3;
        __syncthreads();
        const bf16* srcA = aplane + ((n * 18 + ay + ky) * 18 + (ax + kx)) * 64;
#pragma unroll
        for (int jj = 0; jj < 8; jj++) {
            int j = (jj + mrow) & 7;
            *(uint4*)(sArow + j * 8) = *(const uint4*)(srcA + j * 8);
        }
        const bf16* srcB = g_w2s + (tap * 128 + brow) * 64 + bhalf * 32;
#pragma unroll
        for (int jj = 0; jj < 4; jj++) {
            int j = (jj + brow) & 3;
            *(uint4*)(sBrow + j * 8) = *(const uint4*)(srcB + j * 8);
        }
        __syncthreads();
#pragma unroll
        for (int kc = 0; kc < 4; kc++) {
            uint32_t koff = (uint32_t)(kc * 16) * 2;
            uint32_t ah0, ah1, ah2, ah3, al0, al1, al2, al3;
            ldsm4(aAddrH + koff, ah0, ah1, ah2, ah3);
            ldsm4(aAddrL + koff, al0, al1, al2, al3);
#pragma unroll
            for (int nt2 = 0; nt2 < 8; nt2++) {
                uint32_t r0, r1, r2, r3;
                ldsm4(bAddr0 + koff + (uint32_t)(nt2 * 16 * STR) * 2, r0, r1, r2, r3);
                mma16816(acc[2 * nt2],     ah0, ah1, ah2, ah3, r0, r2);
                mma16816(acc[2 * nt2 + 1], ah0, ah1, ah2, ah3, r1, r3);
                mma16816(acc[2 * nt2],     al0, al1, al2, al3, r0, r2);
                mma16816(acc[2 * nt2 + 1], al0, al1, al2, al3, r1, r3);
            }
        }
    }

    // epilogue: pool(2x2) via shfl over corner lanes, bias+relu, hi/lo store
    float alpha = g_alpha[1];
    int t2 = lane & 3;
    bool wr = (lane & 12) == 0;
    int blk0 = wid * 4 + (lane >> 4);
#pragma unroll
    for (int nt = 0; nt < 16; nt++) {
        float v0 = acc[nt][0], v1 = acc[nt][1], v2 = acc[nt][2], v3 = acc[nt][3];
        v0 = fmaxf(v0, __shfl_xor_sync(0xffffffffu, v0, 4));
        v0 = fmaxf(v0, __shfl_xor_sync(0xffffffffu, v0, 8));
        v1 = fmaxf(v1, __shfl_xor_sync(0xffffffffu, v1, 4));
        v1 = fmaxf(v1, __shfl_xor_sync(0xffffffffu, v1, 8));
        v2 = fmaxf(v2, __shfl_xor_sync(0xffffffffu, v2, 4));
        v2 = fmaxf(v2, __shfl_xor_sync(0xffffffffu, v2, 8));
        v3 = fmaxf(v3, __shfl_xor_sync(0xffffffffu, v3, 4));
        v3 = fmaxf(v3, __shfl_xor_sync(0xffffffffu, v3, 8));
        if (wr) {
            int oc = nt * 8 + t2 * 2;
            float bi0 = sbias[oc], bi1 = sbias[oc + 1];
#pragma unroll
            for (int q = 0; q < 2; q++) {
                int blk = blk0 + q * 2;
                float w0 = fmaxf(alpha * (q ? v2 : v0) + bi0, 0.f);
                float w1 = fmaxf(alpha * (q ? v3 : v1) + bi1, 0.f);
                bf16 h0 = __float2bfloat16(w0); bf16 l0 = __float2bfloat16(w0 - __bfloat162float(h0));
                bf16 h1 = __float2bfloat16(w1); bf16 l1 = __float2bfloat16(w1 - __bfloat162float(h1));
                int py = h * 4 + (blk >> 3), px = blk & 7;
                int idx = ((n * 10 + py + 1) * 10 + px + 1) * 128 + oc;
                ushort2 hs; hs.x = __bfloat16_as_ushort(h0); hs.y = __bfloat16_as_ushort(h1);
                ushort2 ls; ls.x = __bfloat16_as_ushort(l0); ls.y = __bfloat16_as_ushort(l1);
                *(ushort2*)((unsigned short*)G_A2H + idx) = hs;
                *(ushort2*)((unsigned short*)G_A2L + idx) = ls;
            }
        }
    }
}

// ========================= conv3: 128->256 (mma.sync) =======================
// CTA = 2 images (128 M-rows), N=256, 512 threads (16 warps: 8 m-tiles x 2 n).
// M-row m: img=m>>6, b=(m>>2)&15 (s index), c=m&3; y=(b>>2)*2+(c>>1), x=(b&3)*2+(c&1)
#define C3_SA_H 0
#define C3_SA_L (128 * STR * 2)
#define C3_SB (2 * 128 * STR * 2)
#define C3_SBIAS (C3_SB + 256 * STR * 2)
#define C3_SMEM (C3_SBIAS + 1024 + 16)
__global__ __launch_bounds__(512, 1) void k_conv3m(const float* __restrict__ b3) {
    extern __shared__ __align__(16) char smem[];
    uint32_t sbase = smem_u32(smem);
    float* sbias = (float*)(smem + C3_SBIAS);
    int tid = threadIdx.x, wid = tid >> 5, lane = tid & 31;
    int wm = wid & 7, wn = wid >> 3;
    int n0 = blockIdx.x * 2;
    if (tid < 256) sbias[tid] = b3[tid];

    // A staging: 128 rows x 2 planes x 2 halves = 512 units
    int arow = tid >> 2, aplane_i = (tid >> 1) & 1, ahalf = tid & 1;
    int img_l = arow >> 6, bblk = (arow >> 2) & 15, corn = arow & 3;
    int ay = (bblk >> 2) * 2 + (corn >> 1);
    int ax = (bblk & 3) * 2 + (corn & 1);
    const bf16* aplane = aplane_i ? G_A2L : G_A2H;
    bf16* sArow = (bf16*)(smem + (aplane_i ? C3_SA_L : C3_SA_H)) + arow * STR + ahalf * 32;
    // B staging: 256 rows x 2 halves
    int brow = tid >> 1, bhalf = tid & 1;
    bf16* sBrow = (bf16*)(smem + C3_SB) + brow * STR + bhalf * 32;

    float acc[16][4];
#pragma unroll
    for (int i = 0; i < 16; i++)
#pragma unroll
        for (int j = 0; j < 4; j++) acc[i][j] = 0.f;

    int arow_l = wm * 16 + (lane & 15);
    int khalf = ((lane >> 4) & 1) * 8;
    uint32_t aAddrH = sbase + C3_SA_H + (uint32_t)(arow_l * STR + khalf) * 2;
    uint32_t aAddrL = sbase + C3_SA_L + (uint32_t)(arow_l * STR + khalf) * 2;
    uint32_t bAddr0 = sbase + C3_SB + (uint32_t)((wn * 128 + (lane & 15)) * STR + khalf) * 2;

    for (int st = 0; st < 18; st++) {
        int tap = st >> 1, chalf = (st & 1) * 64;
        int ky = tap / 3, kx = tap - ky * 3;
        __syncthreads();
        const bf16* srcA = aplane + (((n0 + img_l) * 10 + ay + ky) * 10 + (ax + kx)) * 128 + chalf + ahalf * 32;
#pragma unroll
        for (int jj = 0; jj < 4; jj++) {
            int j = (jj + arow) & 3;
            *(uint4*)(sArow + j * 8) = *(const uint4*)(srcA + j * 8);
        }
        const bf16* srcB = g_w3s + (tap * 256 + brow) * 128 + chalf + bhalf * 32;
#pragma unroll
        for (int jj = 0; jj < 4; jj++) {
            int j = (jj + brow) & 3;
            *(uint4*)(sBrow + j * 8) = *(const uint4*)(srcB + j * 8);
        }
        __syncthreads();
#pragma unroll
        for (int kc = 0; kc < 4; kc++) {
            uint32_t koff = (uint32_t)(kc * 16) * 2;
            uint32_t ah0, ah1, ah2, ah3, al0, al1, al2, al3;
            ldsm4(aAddrH + koff, ah0, ah1, ah2, ah3);
            ldsm4(aAddrL + koff, al0, al1, al2, al3);
#pragma unroll
            for (int nt2 = 0; nt2 < 8; nt2++) {
                uint32_t r0, r1, r2, r3;
                ldsm4(bAddr0 + koff + (uint32_t)(nt2 * 16 * STR) * 2, r0, r1, r2, r3);
                mma16816(acc[2 * nt2],     ah0, ah1, ah2, ah3, r0, r2);
                mma16816(acc[2 * nt2 + 1], ah0, ah1, ah2, ah3, r1, r3);
                mma16816(acc[2 * nt2],     al0, al1, al2, al3, r0, r2);
                mma16816(acc[2 * nt2 + 1], al0, al1, al2, al3, r1, r3);
            }
        }
    }

    float alpha = g_alpha[2];
    int t2 = lane & 3;
    bool wr = (lane & 12) == 0;
    int blk0 = (wm & 3) * 4 + (lane >> 4);
    int imgo = n0 + (wm >> 2);
#pragma unroll
    for (int nt = 0; nt < 16; nt++) {
        float v0 = acc[nt][0], v1 = acc[nt][1], v2 = acc[nt][2], v3 = acc[nt][3];
        v0 = fmaxf(v0, __shfl_xor_sync(0xffffffffu, v0, 4));
        v0 = fmaxf(v0, __shfl_xor_sync(0xffffffffu, v0, 8));
        v1 = fmaxf(v1, __shfl_xor_sync(0xffffffffu, v1, 4));
        v1 = fmaxf(v1, __shfl_xor_sync(0xffffffffu, v1, 8));
        v2 = fmaxf(v2, __shfl_xor_sync(0xffffffffu, v2, 4));
        v2 = fmaxf(v2, __shfl_xor_sync(0xffffffffu, v2, 8));
        v3 = fmaxf(v3, __shfl_xor_sync(0xffffffffu, v3, 4));
        v3 = fmaxf(v3, __shfl_xor_sync(0xffffffffu, v3, 8));
        if (wr) {
            int oc = wn * 128 + nt * 8 + t2 * 2;
            float bi0 = sbias[oc], bi1 = sbias[oc + 1];
#pragma unroll
            for (int q = 0; q < 2; q++) {
                int blk = blk0 + q * 2;
                float w0 = fmaxf(alpha * (q ? v2 : v0) + bi0, 0.f);
                float w1 = fmaxf(alpha * (q ? v3 : v1) + bi1, 0.f);
                bf16 h0 = __float2bfloat16(w0); bf16 l0 = __float2bfloat16(w0 - __bfloat162float(h0));
                bf16 h1 = __float2bfloat16(w1); bf16 l1 = __float2bfloat16(w1 - __bfloat162float(h1));
                int idx = (imgo * 16 + blk) * 256 + oc;
                ushort2 hs; hs.x = __bfloat16_as_ushort(h0); hs.y = __bfloat16_as_ushort(h1);
                ushort2 ls; ls.x = __bfloat16_as_ushort(l0); ls.y = __bfloat16_as_ushort(l1);
                *(ushort2*)((unsigned short*)g_act3h + idx) = hs;
                *(ushort2*)((unsigned short*)g_act3l + idx) = ls;
            }
        }
    }
}

// ========================= fc1 (mma.sync, split-K 8) ========================
__global__ __launch_bounds__(256, 2) void k_fc1m() {
    extern __shared__ __align__(16) char smem[];
    uint32_t sbase = smem_u32(smem);
    int tid = threadIdx.x, wid = tid >> 5, lane = tid & 31;
    int m0 = blockIdx.x * 128, o0 = blockIdx.y * 128, k0 = blockIdx.z * 512;

    int mrow = tid >> 1, plane = tid & 1;
    const bf16* aplane = plane ? g_act3l : g_act3h;
    bf16* sArow = (bf16*)(smem + (plane ? SA_L : SA_H)) + mrow * STR;
    int brow = tid >> 1, bhalf = tid & 1;
    bf16* sBrow = (bf16*)(smem + SB_OFF) + brow * STR + bhalf * 32;

    float acc[16][4];
#pragma unroll
    for (int i = 0; i < 16; i++)
#pragma unroll
        for (int j = 0; j < 4; j++) acc[i][j] = 0.f;

    int arow_l = wid * 16 + (lane & 15);
    int khalf = ((lane >> 4) & 1) * 8;
    uint32_t aAddrH = sbase + SA_H + (uint32_t)(arow_l * STR + khalf) * 2;
    uint32_t aAddrL = sbase + SA_L + (uint32_t)(arow_l * STR + khalf) * 2;
    uint32_t bAddr0 = sbase + SB_OFF + (uint32_t)((lane & 15) * STR + khalf) * 2;

    for (int st = 0; st < 8; st++) {
        int koff = k0 + st * 64;
        __syncthreads();
        const bf16* srcA = aplane + (m0 + mrow) * 4096 + koff;
#pragma unroll
        for (int jj = 0; jj < 8; jj++) {
            int j = (jj + mrow) & 7;
            *(uint4*)(sArow + j * 8) = *(const uint4*)(srcA + j * 8);
        }
        const bf16* srcB = g_wf1s + (o0 + brow) * 4096 + koff + bhalf * 32;
#pragma unroll
        for (int jj = 0; jj < 4; jj++) {
            int j = (jj + brow) & 3;
            *(uint4*)(sBrow + j * 8) = *(const uint4*)(srcB + j * 8);
        }
        __syncthreads();
#pragma unroll
        for (int kc = 0; kc < 4; kc++) {
            uint32_t kofs = (uint32_t)(kc * 16) * 2;
            uint32_t ah0, ah1, ah2, ah3, al0, al1, al2, al3;
            ldsm4(aAddrH + kofs, ah0, ah1, ah2, ah3);
            ldsm4(aAddrL + kofs, al0, al1, al2, al3);
#pragma unroll
            for (int nt2 = 0; nt2 < 8; nt2++) {
                uint32_t r0, r1, r2, r3;
                ldsm4(bAddr0 + kofs + (uint32_t)(nt2 * 16 * STR) * 2, r0, r1, r2, r3);
                mma16816(acc[2 * nt2],     ah0, ah1, ah2, ah3, r0, r2);
                mma16816(acc[2 * nt2 + 1], ah0, ah1, ah2, ah3, r1, r3);
                mma16816(acc[2 * nt2],     al0, al1, al2, al3, r0, r2);
                mma16816(acc[2 * nt2 + 1], al0, al1, al2, al3, r1, r3);
            }
        }
    }

    float* dst = g_fc1p + (long)blockIdx.z * (NB * 256);
    int g = lane >> 2, t2 = lane & 3;
    int row = m0 + wid * 16 + g;
#pragma unroll
    for (int nt = 0; nt < 16; nt++) {
        int col = o0 + nt * 8 + t2 * 2;
        float2 p0; p0.x = acc[nt][0]; p0.y = acc[nt][1];
        float2 p1; p1.x = acc[nt][2]; p1.y = acc[nt][3];
        *(float2*)(dst + row * 256 + col) = p0;
        *(float2*)(dst + (row + 8) * 256 + col) = p1;
    }
}

__global__ void k_fc1red(const float* __restrict__ bf1) {
    int i = blockIdx.x * 256 + threadIdx.x;
    int o = i & 255;
    float al = g_alpha[3];
    float v = 0.f;
#pragma unroll
    for (int s = 0; s < 8; s++) v += g_fc1p[(long)s * NB * 256 + i];
    g_fc1[i] = fmaxf(al * v + bf1[o], 0.f);
}

// ========================= fc2 ==============================================
__global__ void k_fc2(const float* __restrict__ bf2, float* __restrict__ out) {
    int i = blockIdx.x * blockDim.x + threadIdx.x;
    if (i >= NB * 10) return;
    int n = i / 10, o = i % 10;
    float al = g_alpha[4];
    float s = 0.f;
    const float* a = &g_fc1[n * 256];
    const float* w = &g_wf2t[o * 256];
#pragma unroll 8
    for (int k = 0; k < 256; k++) s += a[k] * w[k];
    out[i] = al * s + bf2[o];
}

// ========================= launch ===========================================
extern "C" void kernel_launch(void* const* d_in, const int* in_sizes, int n_in,
                              void* d_out, int out_size) {
    const float* x   = (const float*)d_in[0];
    const float* w1  = (const float*)d_in[1];
    const float* b1  = (const float*)d_in[2];
    const float* w2  = (const float*)d_in[3];
    const float* b2  = (const float*)d_in[4];
    const float* w3  = (const float*)d_in[5];
    const float* b3  = (const float*)d_in[6];
    const float* wf1 = (const float*)d_in[7];
    const float* bf1 = (const float*)d_in[8];
    const float* wf2 = (const float*)d_in[9];
    const float* bf2 = (const float*)d_in[10];
    float* out = (float*)d_out;

    static int configured = 0;
    if (!configured) {
        cudaFuncSetAttribute(k_conv2m, cudaFuncAttributeMaxDynamicSharedMemorySize, C2_SMEM);
        cudaFuncSetAttribute(k_conv3m, cudaFuncAttributeMaxDynamicSharedMemorySize, C3_SMEM);
        cudaFuncSetAttribute(k_fc1m,   cudaFuncAttributeMaxDynamicSharedMemorySize, C2_SMEM);
        configured = 1;
    }

    k_zero<<<4096, 256>>>();
    k_tstat1<<<dim3(64, 5), 256>>>(w1, w2, w3, wf1, wf2);
    k_tfin1<<<5, 64>>>();
    k_tstat2<<<dim3(64, 5), 256>>>(w1, w2, w3, wf1, wf2);
    k_tfin2<<<5, 64>>>();
    k_twrite<<<dim3(256, 5), 256>>>(w1, w2, w3, wf1, wf2);

    k_conv1<<<NB, 256>>>(x, b1);
    k_conv2m<<<NB * 2, 256, C2_SMEM>>>(b2);
    k_conv3m<<<NB / 2, 512, C3_SMEM>>>(b3);
    k_fc1m<<<dim3(8, 2, 8), 256, C2_SMEM>>>();
    k_fc1red<<<NB, 256>>>(bf1);
    k_fc2<<<(NB * 10 + 255) / 256, 256>>>(bf2, out);
}

// round 5
// speedup vs baseline: 9.7776x; 1.7942x over previous
#include <cuda_runtime.h>
#include <cuda_fp16.h>
#include <math.h>
#include <stdint.h>

// ---------------------------------------------------------------------------
// TernaryCIFAR10Net forward, B=1024 — fp16 single-plane mma.sync version.
//   weights: ternary signs exact in fp16; alpha folded into fp32 epilogue.
//   activations: fp16 (rel quant ~2^-11 -> final rel_err ~5e-4 << 1e-3).
//   convs: halo staged ONCE per CTA; ldmatrix directly from halo with
//   per-tap computed row addresses; weights double-buffered via cp.async.
// ---------------------------------------------------------------------------

#define NB 1024
typedef unsigned long long u64;
typedef __half h16;

__device__ __forceinline__ uint32_t smem_u32(const void* p) {
    uint32_t a;
    asm("{ .reg .u64 t; cvta.to.shared.u64 t, %1; cvt.u32.u64 %0, t; }" : "=r"(a) : "l"(p));
    return a;
}
__device__ __forceinline__ void ldsm4(uint32_t addr, uint32_t& r0, uint32_t& r1,
                                      uint32_t& r2, uint32_t& r3) {
    asm volatile("ldmatrix.sync.aligned.m8n8.x4.shared.b16 {%0,%1,%2,%3}, [%4];"
                 : "=r"(r0), "=r"(r1), "=r"(r2), "=r"(r3) : "r"(addr));
}
__device__ __forceinline__ void mmaf16(float* d, uint32_t a0, uint32_t a1, uint32_t a2,
                                       uint32_t a3, uint32_t b0, uint32_t b1) {
    asm volatile("mma.sync.aligned.m16n8k16.row.col.f32.f16.f16.f32 "
                 "{%0,%1,%2,%3}, {%4,%5,%6,%7}, {%8,%9}, {%0,%1,%2,%3};"
                 : "+f"(d[0]), "+f"(d[1]), "+f"(d[2]), "+f"(d[3])
                 : "r"(a0), "r"(a1), "r"(a2), "r"(a3), "r"(b0), "r"(b1));
}
#define CP_ASYNC16(dst, src) \
    asm volatile("cp.async.cg.shared.global [%0], [%1], 16;" :: "r"(dst), "l"(src))
#define CP_COMMIT() asm volatile("cp.async.commit_group;" ::: "memory")
#define CP_WAIT1()  asm volatile("cp.async.wait_group 1;" ::: "memory")
#define CP_WAIT0()  asm volatile("cp.async.wait_group 0;" ::: "memory")

// fp32x2 helpers for conv1
__device__ __forceinline__ u64 f2fma(u64 a, u64 b, u64 c) {
    u64 d; asm("fma.rn.f32x2 %0, %1, %2, %3;" : "=l"(d) : "l"(a), "l"(b), "l"(c)); return d;
}
__device__ __forceinline__ u64 fdup(float v) {
    u64 d; asm("mov.b64 %0, {%1, %1};" : "=l"(d) : "f"(v)); return d;
}
__device__ __forceinline__ float2 f2unpack(u64 d) {
    float2 r; asm("mov.b64 {%0, %1}, %2;" : "=f"(r.x), "=f"(r.y) : "l"(d)); return r;
}

// ========================= device scratch ===================================
#define A1SZ (NB * 18 * 18 * 64)
#define A2SZ (NB * 10 * 10 * 128)
__device__ __align__(16) h16 g_a1[A1SZ];          // [n][18][18][64] padded
__device__ __align__(16) h16 g_a2[A2SZ];          // [n][10][10][128] padded
__device__ __align__(16) h16 g_act3[NB * 16 * 256]; // [n][s][c]
__device__ float g_fc1p[8 * NB * 256];
__device__ float g_fc1[NB * 256];

__device__ float g_w1t[27 * 64];                       // fp32 sign [k][oc]
__device__ __align__(16) h16 g_w2s[9 * 128 * 72];      // [tap][oc][ic pad72]
__device__ __align__(16) h16 g_w3s[9 * 2 * 256 * 72];  // [tap][ichalf][oc][ic64 pad72]
__device__ __align__(16) h16 g_wf1s[256 * 4096];       // [o][k'], k'=s*256+c
__device__ float g_wf2t[10 * 256];

__device__ float g_part[5][64];
__device__ float g_cnt[5][64];
__device__ float g_delta[5];
__device__ float g_alpha[5];

__constant__ int c_n[5] = {64 * 3 * 9, 128 * 64 * 9, 256 * 128 * 9, 256 * 4096, 10 * 256};

__device__ __forceinline__ const float* pick_src(int t, const float* a, const float* b,
                                                 const float* c, const float* d, const float* e) {
    switch (t) { case 0: return a; case 1: return b; case 2: return c; case 3: return d; default: return e; }
}

// ========================= ternarization ====================================
__global__ void k_tstat1(const float* __restrict__ a, const float* __restrict__ b,
                         const float* __restrict__ c, const float* __restrict__ d,
                         const float* __restrict__ e) {
    int t = blockIdx.y;
    const float* w = pick_src(t, a, b, c, d, e);
    int n = c_n[t];
    float s = 0.f;
    for (int i = blockIdx.x * 256 + threadIdx.x; i < n; i += 64 * 256) s += fabsf(w[i]);
    __shared__ float sm[256];
    sm[threadIdx.x] = s; __syncthreads();
    for (int st = 128; st > 0; st >>= 1) {
        if (threadIdx.x < st) sm[threadIdx.x] += sm[threadIdx.x + st];
        __syncthreads();
    }
    if (threadIdx.x == 0) g_part[t][blockIdx.x] = sm[0];
}
__global__ void k_tfin1() {
    int t = blockIdx.x, tid = threadIdx.x;
    __shared__ float sm[64];
    sm[tid] = g_part[t][tid]; __syncthreads();
    for (int st = 32; st > 0; st >>= 1) {
        if (tid < st) sm[tid] += sm[tid + st];
        __syncthreads();
    }
    if (tid == 0) g_delta[t] = 0.7f * sm[0] / (float)c_n[t];
}
__global__ void k_tstat2(const float* __restrict__ a, const float* __restrict__ b,
                         const float* __restrict__ c, const float* __restrict__ d,
                         const float* __restrict__ e) {
    int t = blockIdx.y;
    const float* w = pick_src(t, a, b, c, d, e);
    int n = c_n[t];
    float dlt = g_delta[t];
    float s = 0.f, cn = 0.f;
    for (int i = blockIdx.x * 256 + threadIdx.x; i < n; i += 64 * 256) {
        float av = fabsf(w[i]);
        if (av > dlt) { s += av; cn += 1.f; }
    }
    __shared__ float sm[256], sc[256];
    sm[threadIdx.x] = s; sc[threadIdx.x] = cn; __syncthreads();
    for (int st = 128; st > 0; st >>= 1) {
        if (threadIdx.x < st) { sm[threadIdx.x] += sm[threadIdx.x + st]; sc[threadIdx.x] += sc[threadIdx.x + st]; }
        __syncthreads();
    }
    if (threadIdx.x == 0) { g_part[t][blockIdx.x] = sm[0]; g_cnt[t][blockIdx.x] = sc[0]; }
}
__global__ void k_tfin2() {
    int t = blockIdx.x, tid = threadIdx.x;
    __shared__ float sm[64], sc[64];
    sm[tid] = g_part[t][tid]; sc[tid] = g_cnt[t][tid]; __syncthreads();
    for (int st = 32; st > 0; st >>= 1) {
        if (tid < st) { sm[tid] += sm[tid + st]; sc[tid] += sc[tid + st]; }
        __syncthreads();
    }
    if (tid == 0) g_alpha[t] = sm[0] / fmaxf(sc[0], 1.f);
}
__global__ void k_twrite(const float* __restrict__ a, const float* __restrict__ b,
                         const float* __restrict__ c, const float* __restrict__ d,
                         const float* __restrict__ e) {
    int t = blockIdx.y;
    const float* w = pick_src(t, a, b, c, d, e);
    int n = c_n[t];
    float dlt = g_delta[t];
    for (int i = blockIdx.x * 256 + threadIdx.x; i < n; i += 256 * 256) {
        float v = w[i];
        float s = (fabsf(v) > dlt) ? (v > 0.f ? 1.f : -1.f) : 0.f;
        switch (t) {
            case 0: { int oc = i / 27,   r = i % 27;  g_w1t[r * 64 + oc] = s; } break;
            case 1: { int oc = i / 576,  r = i % 576;  int ic = r / 9, k = r % 9;
                      g_w2s[(k * 128 + oc) * 72 + ic] = __float2half(s); } break;
            case 2: { int oc = i / 1152, r = i % 1152; int ic = r / 9, k = r % 9;
                      g_w3s[((k * 2 + (ic >> 6)) * 256 + oc) * 72 + (ic & 63)] = __float2half(s); } break;
            case 3: { int o = i >> 12, k = i & 4095; int ch = k >> 4, s4 = k & 15;
                      g_wf1s[o * 4096 + s4 * 256 + ch] = __float2half(s); } break;
            default: g_wf2t[i] = s;
        }
    }
}

// ========================= zero the padded borders ==========================
__global__ void k_zerob() {
    int n = blockIdx.x, which = blockIdx.y, tid = threadIdx.x;
    uint4 z = make_uint4(0, 0, 0, 0);
    if (which == 0) {
        for (int i = tid; i < 544; i += 256) {   // 68 border px * 8 uint4 (64ch)
            int pb = i >> 3, j = i & 7, yy, xx;
            if (pb < 18)      { yy = 0;  xx = pb; }
            else if (pb < 36) { yy = 17; xx = pb - 18; }
            else { int e = pb - 36; yy = 1 + (e >> 1); xx = (e & 1) * 17; }
            *(uint4*)((char*)(g_a1 + ((n * 18 + yy) * 18 + xx) * 64) + j * 16) = z;
        }
    } else {
        for (int i = tid; i < 576; i += 256) {   // 36 border px * 16 uint4 (128ch)
            int pb = i >> 4, j = i & 15, yy, xx;
            if (pb < 10)      { yy = 0; xx = pb; }
            else if (pb < 20) { yy = 9; xx = pb - 10; }
            else { int e = pb - 20; yy = 1 + (e >> 1); xx = (e & 1) * 9; }
            *(uint4*)((char*)(g_a2 + ((n * 10 + yy) * 10 + xx) * 128) + j * 16) = z;
        }
    }
}

// ========================= conv1: 3->64 (FFMA2) =============================
__global__ __launch_bounds__(256) void k_conv1(const float* __restrict__ x,
                                               const float* __restrict__ b1) {
    int n = blockIdx.x, tid = threadIdx.x;
    __shared__ float sin1[3 * 34 * 34];
    __shared__ float sw[27 * 64];
    __shared__ float sb[64];
    __shared__ float sal;

    for (int i = tid; i < 3 * 34 * 34; i += 256) {
        int c = i / 1156, r = i % 1156, y = r / 34, xx = r % 34;
        float v = 0.f;
        if (y >= 1 && y <= 32 && xx >= 1 && xx <= 32)
            v = x[((n * 3 + c) * 32 + (y - 1)) * 32 + (xx - 1)];
        sin1[i] = v;
    }
    for (int i = tid; i < 27 * 64; i += 256) sw[i] = g_w1t[i];
    if (tid < 64) sb[tid] = b1[tid];
    if (tid == 0) sal = g_alpha[0];
    __syncthreads();

    int ph = tid >> 4, pw = tid & 15;
    float p[3][4][4];
#pragma unroll
    for (int c = 0; c < 3; c++)
#pragma unroll
        for (int i = 0; i < 4; i++)
#pragma unroll
            for (int j = 0; j < 4; j++)
                p[c][i][j] = sin1[c * 1156 + (2 * ph + i) * 34 + (2 * pw + j)];
    float alpha = sal;
    int obase = ((n * 18 + ph + 1) * 18 + (pw + 1)) * 64;

    for (int g = 0; g < 8; g++) {
        u64 acc[4][4];
#pragma unroll
        for (int i = 0; i < 4; i++)
#pragma unroll
            for (int j = 0; j < 4; j++) acc[i][j] = 0ull;
#pragma unroll
        for (int c = 0; c < 3; c++)
#pragma unroll
            for (int ky = 0; ky < 3; ky++)
#pragma unroll
                for (int kx = 0; kx < 3; kx++) {
                    int k = c * 9 + ky * 3 + kx;
                    u64 a00 = fdup(p[c][ky][kx]),     a01 = fdup(p[c][ky][kx + 1]);
                    u64 a10 = fdup(p[c][ky + 1][kx]), a11 = fdup(p[c][ky + 1][kx + 1]);
#pragma unroll
                    for (int pr = 0; pr < 4; pr++) {
                        u64 bw = *(const u64*)&sw[k * 64 + g * 8 + pr * 2];
                        acc[pr][0] = f2fma(a00, bw, acc[pr][0]);
                        acc[pr][1] = f2fma(a01, bw, acc[pr][1]);
                        acc[pr][2] = f2fma(a10, bw, acc[pr][2]);
                        acc[pr][3] = f2fma(a11, bw, acc[pr][3]);
                    }
                }
        unsigned short hh[8];
#pragma unroll
        for (int pr = 0; pr < 4; pr++) {
            float2 v0 = f2unpack(acc[pr][0]), v1 = f2unpack(acc[pr][1]);
            float2 v2 = f2unpack(acc[pr][2]), v3 = f2unpack(acc[pr][3]);
            float lo = fmaxf(fmaxf(v0.x, v1.x), fmaxf(v2.x, v3.x));
            float hi = fmaxf(fmaxf(v0.y, v1.y), fmaxf(v2.y, v3.y));
            float vl = fmaxf(alpha * lo + sb[g * 8 + pr * 2],     0.f);
            float vh = fmaxf(alpha * hi + sb[g * 8 + pr * 2 + 1], 0.f);
            hh[pr * 2]     = __half_as_ushort(__float2half(vl));
            hh[pr * 2 + 1] = __half_as_ushort(__float2half(vh));
        }
        *(uint4*)(g_a1 + obase + g * 8) = *(uint4*)hh;
    }
}

// ========================= conv2: 64->128 ===================================
// CTA = half image: M=128 rows (pool-permuted), N=128 oc, 256 thr (8 warps).
// Halo (10x18 px, 64ch) staged once; B (per tap) double-buffered via cp.async.
#define C2_HALO 0
#define C2_B0 25984
#define C2_B1 44416
#define C2_BIAS 62848
#define C2_SMEM 63376
__global__ __launch_bounds__(256, 2) void k_conv2f(const float* __restrict__ b2) {
    extern __shared__ __align__(128) char smem[];
    uint32_t sb = smem_u32(smem);
    int tid = threadIdx.x, wid = tid >> 5, lane = tid & 31;
    int n = blockIdx.x >> 1, h = blockIdx.x & 1;
    float* sbias = (float*)(smem + C2_BIAS);
    if (tid < 128) sbias[tid] = b2[tid];

    // halo: rows 8h..8h+9 of padded 18x18, each px = 64 ch (128B)
    const char* hsrc = (const char*)(g_a1 + (n * 18 + h * 8) * 18 * 64);
    for (int i = tid; i < 1440; i += 256) {
        int pp = i >> 3, j = i & 7;
        uint32_t dst = C2_HALO + pp * 144 + (((pp / 18) & 1) << 5) + j * 16;
        *(uint4*)(smem + dst) = *(const uint4*)(hsrc + i * 16);
    }
    {   // prefetch B tap0
        const char* bsrc = (const char*)g_w2s;
        for (int i = tid; i < 1152; i += 256) CP_ASYNC16(sb + C2_B0 + i * 16, bsrc + i * 16);
        CP_COMMIT();
    }

    int mrow = wid * 16 + (lane & 15);
    int b = mrow >> 2, c = mrow & 3;
    int y = ((b >> 3) << 1) + (c >> 1);   // 0..7 (local)
    int xx = ((b & 7) << 1) + (c & 1);    // 0..15
    uint32_t khalf16 = (uint32_t)((lane >> 4) << 4);
    uint32_t bRowOff = (uint32_t)(lane & 15) * 144 + khalf16;

    float acc[16][4];
#pragma unroll
    for (int i = 0; i < 16; i++)
#pragma unroll
        for (int j = 0; j < 4; j++) acc[i][j] = 0.f;

    for (int tap = 0; tap < 9; tap++) {
        if (tap < 8) {
            const char* bsrc = (const char*)g_w2s + (tap + 1) * 18432;
            uint32_t bdst = sb + ((tap & 1) ? C2_B0 : C2_B1);
            for (int i = tid; i < 1152; i += 256) CP_ASYNC16(bdst + i * 16, bsrc + i * 16);
            CP_COMMIT();
            CP_WAIT1();
        } else {
            CP_WAIT0();
        }
        __syncthreads();
        int ky = tap / 3, kx = tap - ky * 3;
        int hy = y + ky;
        uint32_t aBase = sb + C2_HALO + (uint32_t)(hy * 18 + xx + kx) * 144 +
                         (uint32_t)((hy & 1) << 5) + khalf16;
        uint32_t bBuf = sb + ((tap & 1) ? C2_B1 : C2_B0);
#pragma unroll
        for (int kc = 0; kc < 4; kc++) {
            uint32_t a0, a1, a2, a3;
            ldsm4(aBase + kc * 32, a0, a1, a2, a3);
#pragma unroll
            for (int nt2 = 0; nt2 < 8; nt2++) {
                uint32_t r0, r1, r2, r3;
                ldsm4(bBuf + bRowOff + nt2 * 2304 + kc * 32, r0, r1, r2, r3);
                mmaf16(acc[2 * nt2],     a0, a1, a2, a3, r0, r2);
                mmaf16(acc[2 * nt2 + 1], a0, a1, a2, a3, r1, r3);
            }
        }
        __syncthreads();
    }

    float alpha = g_alpha[1];
    int t2 = lane & 3;
    bool wr = (lane & 12) == 0;
    int blk0 = wid * 4 + (lane >> 4);
#pragma unroll
    for (int nt = 0; nt < 16; nt++) {
        float v0 = acc[nt][0], v1 = acc[nt][1], v2 = acc[nt][2], v3 = acc[nt][3];
        v0 = fmaxf(v0, __shfl_xor_sync(0xffffffffu, v0, 4));
        v0 = fmaxf(v0, __shfl_xor_sync(0xffffffffu, v0, 8));
        v1 = fmaxf(v1, __shfl_xor_sync(0xffffffffu, v1, 4));
        v1 = fmaxf(v1, __shfl_xor_sync(0xffffffffu, v1, 8));
        v2 = fmaxf(v2, __shfl_xor_sync(0xffffffffu, v2, 4));
        v2 = fmaxf(v2, __shfl_xor_sync(0xffffffffu, v2, 8));
        v3 = fmaxf(v3, __shfl_xor_sync(0xffffffffu, v3, 4));
        v3 = fmaxf(v3, __shfl_xor_sync(0xffffffffu, v3, 8));
        if (wr) {
            int oc = nt * 8 + t2 * 2;
            float bi0 = sbias[oc], bi1 = sbias[oc + 1];
#pragma unroll
            for (int q = 0; q < 2; q++) {
                int blk = blk0 + q * 2;
                float w0 = fmaxf(alpha * (q ? v2 : v0) + bi0, 0.f);
                float w1 = fmaxf(alpha * (q ? v3 : v1) + bi1, 0.f);
                int py = h * 4 + (blk >> 3), px = blk & 7;
                ushort2 st;
                st.x = __half_as_ushort(__float2half(w0));
                st.y = __half_as_ushort(__float2half(w1));
                *(ushort2*)((unsigned short*)g_a2 + ((n * 10 + py + 1) * 10 + px + 1) * 128 + oc) = st;
            }
        }
    }
}

// ========================= conv3: 128->256 ==================================
// CTA = 2 images: M=128 rows, N=256 oc, 512 thr (16 warps: 8 m x 2 n).
#define C3_HALO 0
#define C3_B0 54432
#define C3_B1 128160
#define C3_BIAS 201888
#define C3_SMEM 202928
__global__ __launch_bounds__(512, 1) void k_conv3f(const float* __restrict__ b3) {
    extern __shared__ __align__(128) char smem[];
    uint32_t sb = smem_u32(smem);
    int tid = threadIdx.x, wid = tid >> 5, lane = tid & 31;
    int wm = wid & 7, wn = wid >> 3;
    int n0 = blockIdx.x * 2;
    float* sbias = (float*)(smem + C3_BIAS);
    if (tid < 256) sbias[tid] = b3[tid];

    // halo: 2 images x 100 px, each px = 128 ch (256B), stride 272B + parity 32B
    for (int i = tid; i < 3200; i += 512) {
        int pp = i >> 4, j = i & 15;
        int im = pp / 100, pl = pp - im * 100;
        uint32_t dst = C3_HALO + pp * 272 + (uint32_t)(((pl / 10) & 1) << 5) + j * 16;
        *(uint4*)(smem + dst) =
            *(const uint4*)((const char*)(g_a2 + ((n0 + im) * 100 + pl) * 128) + j * 16);
    }
    {   // prefetch B tap0 (73728B)
        const char* bsrc = (const char*)g_w3s;
        for (int i = tid; i < 4608; i += 512) CP_ASYNC16(sb + C3_B0 + i * 16, bsrc + i * 16);
        CP_COMMIT();
    }

    int mrow = wm * 16 + (lane & 15);
    int img_l = mrow >> 6;
    int bl = (mrow >> 2) & 15, c = mrow & 3;
    int y = ((bl >> 2) << 1) + (c >> 1);
    int xx = ((bl & 3) << 1) + (c & 1);
    uint32_t khalf16 = (uint32_t)((lane >> 4) << 4);
    uint32_t bRowOff = (uint32_t)((wn << 7) + (lane & 15)) * 144 + khalf16;

    float acc[16][4];
#pragma unroll
    for (int i = 0; i < 16; i++)
#pragma unroll
        for (int j = 0; j < 4; j++) acc[i][j] = 0.f;

    for (int tap = 0; tap < 9; tap++) {
        if (tap < 8) {
            const char* bsrc = (const char*)g_w3s + (tap + 1) * 73728;
            uint32_t bdst = sb + ((tap & 1) ? C3_B0 : C3_B1);
            for (int i = tid; i < 4608; i += 512) CP_ASYNC16(bdst + i * 16, bsrc + i * 16);
            CP_COMMIT();
            CP_WAIT1();
        } else {
            CP_WAIT0();
        }
        __syncthreads();
        int ky = tap / 3, kx = tap - ky * 3;
        int hy = y + ky;
        uint32_t aBase = sb + C3_HALO +
                         (uint32_t)(img_l * 100 + hy * 10 + xx + kx) * 272 +
                         (uint32_t)((hy & 1) << 5) + khalf16;
        uint32_t bBuf = sb + ((tap & 1) ? C3_B1 : C3_B0);
#pragma unroll
        for (int kc = 0; kc < 8; kc++) {
            uint32_t a0, a1, a2, a3;
            ldsm4(aBase + kc * 32, a0, a1, a2, a3);
            uint32_t bK = bBuf + (uint32_t)((kc >> 2) * 36864) + (uint32_t)((kc & 3) * 32);
#pragma unroll
            for (int nt2 = 0; nt2 < 8; nt2++) {
                uint32_t r0, r1, r2, r3;
                ldsm4(bK + bRowOff + nt2 * 2304, r0, r1, r2, r3);
                mmaf16(acc[2 * nt2],     a0, a1, a2, a3, r0, r2);
                mmaf16(acc[2 * nt2 + 1], a0, a1, a2, a3, r1, r3);
            }
        }
        __syncthreads();
    }

    float alpha = g_alpha[2];
    int t2 = lane & 3;
    bool wr = (lane & 12) == 0;
    int blk0 = (wm & 3) * 4 + (lane >> 4);
    int imgo = n0 + (wm >> 2);
#pragma unroll
    for (int nt = 0; nt < 16; nt++) {
        float v0 = acc[nt][0], v1 = acc[nt][1], v2 = acc[nt][2], v3 = acc[nt][3];
        v0 = fmaxf(v0, __shfl_xor_sync(0xffffffffu, v0, 4));
        v0 = fmaxf(v0, __shfl_xor_sync(0xffffffffu, v0, 8));
        v1 = fmaxf(v1, __shfl_xor_sync(0xffffffffu, v1, 4));
        v1 = fmaxf(v1, __shfl_xor_sync(0xffffffffu, v1, 8));
        v2 = fmaxf(v2, __shfl_xor_sync(0xffffffffu, v2, 4));
        v2 = fmaxf(v2, __shfl_xor_sync(0xffffffffu, v2, 8));
        v3 = fmaxf(v3, __shfl_xor_sync(0xffffffffu, v3, 4));
        v3 = fmaxf(v3, __shfl_xor_sync(0xffffffffu, v3, 8));
        if (wr) {
            int oc = wn * 128 + nt * 8 + t2 * 2;
            float bi0 = sbias[oc], bi1 = sbias[oc + 1];
#pragma unroll
            for (int q = 0; q < 2; q++) {
                int blk = blk0 + q * 2;
                float w0 = fmaxf(alpha * (q ? v2 : v0) + bi0, 0.f);
                float w1 = fmaxf(alpha * (q ? v3 : v1) + bi1, 0.f);
                ushort2 st;
                st.x = __half_as_ushort(__float2half(w0));
                st.y = __half_as_ushort(__float2half(w1));
                *(ushort2*)((unsigned short*)g_act3 + (imgo * 16 + blk) * 256 + oc) = st;
            }
        }
    }
}

// ========================= fc1 (split-K 8) ==================================
#define F1_SA 0
#define F1_SB 18432
#define F1_SMEM 36880
__global__ __launch_bounds__(256, 2) void k_fc1f() {
    extern __shared__ __align__(128) char smem[];
    uint32_t sbase = smem_u32(smem);
    int tid = threadIdx.x, wid = tid >> 5, lane = tid & 31;
    int m0 = blockIdx.x * 128, o0 = blockIdx.y * 128, k0 = blockIdx.z * 512;

    int row = tid >> 1, half = tid & 1;

    float acc[16][4];
#pragma unroll
    for (int i = 0; i < 16; i++)
#pragma unroll
        for (int j = 0; j < 4; j++) acc[i][j] = 0.f;

    int arow_l = wid * 16 + (lane & 15);
    uint32_t khalf16 = (uint32_t)((lane >> 4) << 4);
    uint32_t aAddr = sbase + F1_SA + (uint32_t)arow_l * 144 + khalf16;
    uint32_t bAddr0 = sbase + F1_SB + (uint32_t)(lane & 15) * 144 + khalf16;

    for (int st = 0; st < 8; st++) {
        int koff = k0 + st * 64;
        __syncthreads();
        {
            const h16* srcA = g_act3 + (m0 + row) * 4096 + koff + half * 32;
            const h16* srcB = g_wf1s + (o0 + row) * 4096 + koff + half * 32;
            char* dA = smem + F1_SA + row * 144 + half * 64;
            char* dB = smem + F1_SB + row * 144 + half * 64;
#pragma unroll
            for (int j = 0; j < 4; j++) {
                *(uint4*)(dA + j * 16) = *(const uint4*)(srcA + j * 8);
                *(uint4*)(dB + j * 16) = *(const uint4*)(srcB + j * 8);
            }
        }
        __syncthreads();
#pragma unroll
        for (int kc = 0; kc < 4; kc++) {
            uint32_t kofs = (uint32_t)(kc * 32);
            uint32_t a0, a1, a2, a3;
            ldsm4(aAddr + kofs, a0, a1, a2, a3);
#pragma unroll
            for (int nt2 = 0; nt2 < 8; nt2++) {
                uint32_t r0, r1, r2, r3;
                ldsm4(bAddr0 + kofs + nt2 * 2304, r0, r1, r2, r3);
                mmaf16(acc[2 * nt2],     a0, a1, a2, a3, r0, r2);
                mmaf16(acc[2 * nt2 + 1], a0, a1, a2, a3, r1, r3);
            }
        }
    }

    float* dst = g_fc1p + (long)blockIdx.z * (NB * 256);
    int g = lane >> 2, t2 = lane & 3;
    int orow = m0 + wid * 16 + g;
#pragma unroll
    for (int nt = 0; nt < 16; nt++) {
        int col = o0 + nt * 8 + t2 * 2;
        float2 p0; p0.x = acc[nt][0]; p0.y = acc[nt][1];
        float2 p1; p1.x = acc[nt][2]; p1.y = acc[nt][3];
        *(float2*)(dst + orow * 256 + col) = p0;
        *(float2*)(dst + (orow + 8) * 256 + col) = p1;
    }
}

__global__ void k_fc1red(const float* __restrict__ bf1) {
    int i = blockIdx.x * 256 + threadIdx.x;
    int o = i & 255;
    float al = g_alpha[3];
    float v = 0.f;
#pragma unroll
    for (int s = 0; s < 8; s++) v += g_fc1p[(long)s * NB * 256 + i];
    g_fc1[i] = fmaxf(al * v + bf1[o], 0.f);
}

// ========================= fc2 ==============================================
__global__ void k_fc2(const float* __restrict__ bf2, float* __restrict__ out) {
    int i = blockIdx.x * blockDim.x + threadIdx.x;
    if (i >= NB * 10) return;
    int n = i / 10, o = i % 10;
    float al = g_alpha[4];
    float s = 0.f;
    const float* a = &g_fc1[n * 256];
    const float* w = &g_wf2t[o * 256];
#pragma unroll 8
    for (int k = 0; k < 256; k++) s += a[k] * w[k];
    out[i] = al * s + bf2[o];
}

// ========================= launch ===========================================
extern "C" void kernel_launch(void* const* d_in, const int* in_sizes, int n_in,
                              void* d_out, int out_size) {
    const float* x   = (const float*)d_in[0];
    const float* w1  = (const float*)d_in[1];
    const float* b1  = (const float*)d_in[2];
    const float* w2  = (const float*)d_in[3];
    const float* b2  = (const float*)d_in[4];
    const float* w3  = (const float*)d_in[5];
    const float* b3  = (const float*)d_in[6];
    const float* wf1 = (const float*)d_in[7];
    const float* bf1 = (const float*)d_in[8];
    const float* wf2 = (const float*)d_in[9];
    const float* bf2 = (const float*)d_in[10];
    float* out = (float*)d_out;

    static int configured = 0;
    if (!configured) {
        cudaFuncSetAttribute(k_conv2f, cudaFuncAttributeMaxDynamicSharedMemorySize, C2_SMEM);
        cudaFuncSetAttribute(k_conv3f, cudaFuncAttributeMaxDynamicSharedMemorySize, C3_SMEM);
        cudaFuncSetAttribute(k_fc1f,   cudaFuncAttributeMaxDynamicSharedMemorySize, F1_SMEM);
        configured = 1;
    }

    k_zerob<<<dim3(NB, 2), 256>>>();
    k_tstat1<<<dim3(64, 5), 256>>>(w1, w2, w3, wf1, wf2);
    k_tfin1<<<5, 64>>>();
    k_tstat2<<<dim3(64, 5), 256>>>(w1, w2, w3, wf1, wf2);
    k_tfin2<<<5, 64>>>();
    k_twrite<<<dim3(256, 5), 256>>>(w1, w2, w3, wf1, wf2);

    k_conv1<<<NB, 256>>>(x, b1);
    k_conv2f<<<NB * 2, 256, C2_SMEM>>>(b2);
    k_conv3f<<<NB / 2, 512, C3_SMEM>>>(b3);
    k_fc1f<<<dim3(8, 2, 8), 256, F1_SMEM>>>();
    k_fc1red<<<NB, 256>>>(bf1);
    k_fc2<<<(NB * 10 + 255) / 256, 256>>>(bf2, out);
}